// round 11
// baseline (speedup 1.0000x reference)
#include <cuda_runtime.h>
#include <cuda_bf16.h>
#include <math.h>
#include <stdint.h>

// ---------------------------------------------------------------------------
// Encoder layer: B=1, S=4096, D=1024, H=16, dk=64, F=4096, fp32 in/out.
// GEMMs: tf32 mma.sync, BM=BN=128, 4 warps (64x64 warp tile), 2 CTAs/SM,
// weights pre-transposed to [N,K] so BOTH operands load via ldmatrix.x4.
// Attention: bf16 m16n8k16 flash kernel (R9, unchanged).
// ---------------------------------------------------------------------------

#define S_LEN 4096
#define D_MODEL 1024
#define D_FF 4096
#define NUM_HEADS 16
#define DK 64
#define QKV_N 3072

__device__ float g_h1[S_LEN * D_MODEL];
__device__ __nv_bfloat16 g_Qb[S_LEN * D_MODEL];
__device__ __nv_bfloat16 g_Kb[S_LEN * D_MODEL];
__device__ float g_V [S_LEN * D_MODEL];
__device__ __nv_bfloat16 g_Vt[D_MODEL * S_LEN];   // [dim][key]
__device__ float g_ctx[S_LEN * D_MODEL];
__device__ float g_x1[S_LEN * D_MODEL];
__device__ float g_h2[S_LEN * D_MODEL];
__device__ float g_f1[S_LEN * D_FF];
// transposed weights [N, K]
__device__ float g_W3T[QKV_N * D_MODEL];
__device__ float g_WoT[D_MODEL * D_MODEL];
__device__ float g_W1T[D_FF * D_MODEL];
__device__ float g_W2T[D_MODEL * D_FF];
__device__ float g_b3[QKV_N];

// ---------------------------------------------------------------------------
__device__ __forceinline__ void mma_tf32(float (&d)[4],
    const uint32_t (&a)[4], uint32_t b0, uint32_t b1)
{
    asm volatile(
        "mma.sync.aligned.m16n8k8.row.col.f32.tf32.tf32.f32 "
        "{%0,%1,%2,%3}, {%4,%5,%6,%7}, {%8,%9}, {%0,%1,%2,%3};\n"
        : "+f"(d[0]), "+f"(d[1]), "+f"(d[2]), "+f"(d[3])
        : "r"(a[0]), "r"(a[1]), "r"(a[2]), "r"(a[3]), "r"(b0), "r"(b1));
}
__device__ __forceinline__ void mma_bf16(float (&d)[4],
    const uint32_t (&a)[4], uint32_t b0, uint32_t b1)
{
    asm volatile(
        "mma.sync.aligned.m16n8k16.row.col.f32.bf16.bf16.f32 "
        "{%0,%1,%2,%3}, {%4,%5,%6,%7}, {%8,%9}, {%0,%1,%2,%3};\n"
        : "+f"(d[0]), "+f"(d[1]), "+f"(d[2]), "+f"(d[3])
        : "r"(a[0]), "r"(a[1]), "r"(a[2]), "r"(a[3]), "r"(b0), "r"(b1));
}
__device__ __forceinline__ void ldsm_x4(uint32_t (&d)[4], uint32_t saddr) {
    asm volatile("ldmatrix.sync.aligned.m8n8.x4.shared.b16 {%0,%1,%2,%3}, [%4];"
        : "=r"(d[0]), "=r"(d[1]), "=r"(d[2]), "=r"(d[3]) : "r"(saddr));
}
__device__ __forceinline__ void ldsm_x2(uint32_t& d0, uint32_t& d1, uint32_t saddr) {
    asm volatile("ldmatrix.sync.aligned.m8n8.x2.shared.b16 {%0,%1}, [%2];"
        : "=r"(d0), "=r"(d1) : "r"(saddr));
}
__device__ __forceinline__ uint32_t f2u(float x) { return __float_as_uint(x); }
__device__ __forceinline__ uint32_t smem_u32(const void* p) {
    return (uint32_t)__cvta_generic_to_shared(p);
}
__device__ __forceinline__ uint32_t pack_bf16(float lo, float hi) {
    __nv_bfloat162 v = __floats2bfloat162_rn(lo, hi);
    return *(uint32_t*)&v;
}
#define CP_ASYNC16(dst, src) \
    asm volatile("cp.async.cg.shared.global [%0], [%1], 16;\n" :: "r"(dst), "l"(src))
#define CP_COMMIT() asm volatile("cp.async.commit_group;\n")
#define CP_WAIT(n)  asm volatile("cp.async.wait_group %0;\n" :: "n"(n))

__device__ __forceinline__ float ex2(float x) {
    float y;
    asm("ex2.approx.f32 %0, %1;" : "=f"(y) : "f"(x));
    return y;
}

// ---------------------------------------------------------------------------
// Weight transpose: out[n*K + k] = in[k*N + n]
// ---------------------------------------------------------------------------
__global__ __launch_bounds__(256) void transpose_k(
    const float* __restrict__ in, float* __restrict__ out, int K, int N)
{
    __shared__ float t[32][33];
    const int n0 = blockIdx.x * 32, k0 = blockIdx.y * 32;
    const int x = threadIdx.x & 31, y = threadIdx.x >> 5;   // 32x8
#pragma unroll
    for (int i = 0; i < 32; i += 8)
        t[y + i][x] = in[(size_t)(k0 + y + i) * N + n0 + x];
    __syncthreads();
#pragma unroll
    for (int i = 0; i < 32; i += 8)
        out[(size_t)(n0 + y + i) * K + k0 + x] = t[x][y + i];
}

// Concat biases bq|bk|bv -> b3
__global__ __launch_bounds__(256) void biascat(
    const float* __restrict__ bq, const float* __restrict__ bk,
    const float* __restrict__ bv, float* __restrict__ b3)
{
    const int n = blockIdx.x * 256 + threadIdx.x;
    if (n < QKV_N) {
        const int sel = n >> 10, col = n & 1023;
        const float* b = sel == 0 ? bq : (sel == 1 ? bk : bv);
        b3[n] = b[col];
    }
}

// ---------------------------------------------------------------------------
// V [S,1024] fp32 -> Vt [1024,S] bf16 (transpose + convert)
// ---------------------------------------------------------------------------
__global__ __launch_bounds__(256) void vtrans(
    const float* __restrict__ V, __nv_bfloat16* __restrict__ Vt)
{
    __shared__ float t[64][33];
    const int k0 = blockIdx.x * 64;
    const int d0 = blockIdx.y * 32;
    const int x = threadIdx.x & 31;
    const int y = threadIdx.x >> 5;
#pragma unroll
    for (int i = 0; i < 64; i += 8)
        t[y + i][x] = V[(size_t)(k0 + y + i) * D_MODEL + d0 + x];
    __syncthreads();
    uint32_t* Vt32 = (uint32_t*)Vt;
#pragma unroll
    for (int p = 0; p < 4; p++) {
        const int d = y + 8 * p;
        const int j = x;
        uint32_t v = pack_bf16(t[2 * j][d], t[2 * j + 1][d]);
        Vt32[(size_t)(d0 + d) * (S_LEN / 2) + (k0 >> 1) + j] = v;
    }
}

// ---------------------------------------------------------------------------
// LayerNorm (unbiased var ddof=1, denom = sqrt(var)+eps)
// ---------------------------------------------------------------------------
__global__ __launch_bounds__(256) void ln_kernel(
    const float* __restrict__ x, const float* __restrict__ alpha,
    const float* __restrict__ beta, float* __restrict__ y)
{
    const int row = blockIdx.x;
    const float4* xr = (const float4*)(x + (size_t)row * D_MODEL);
    float4* yr = (float4*)(y + (size_t)row * D_MODEL);
    const int tid = threadIdx.x;

    float4 xl = xr[tid];
    float s = xl.x + xl.y + xl.z + xl.w;

    __shared__ float sh[8];
#pragma unroll
    for (int o = 16; o > 0; o >>= 1) s += __shfl_xor_sync(0xffffffffu, s, o);
    if ((tid & 31) == 0) sh[tid >> 5] = s;
    __syncthreads();
    float mu = 0.f;
#pragma unroll
    for (int i = 0; i < 8; i++) mu += sh[i];
    mu *= (1.0f / D_MODEL);
    __syncthreads();

    float dx = xl.x - mu, dy = xl.y - mu, dz = xl.z - mu, dw = xl.w - mu;
    float v = dx * dx + dy * dy + dz * dz + dw * dw;
#pragma unroll
    for (int o = 16; o > 0; o >>= 1) v += __shfl_xor_sync(0xffffffffu, v, o);
    if ((tid & 31) == 0) sh[tid >> 5] = v;
    __syncthreads();
    float var = 0.f;
#pragma unroll
    for (int i = 0; i < 8; i++) var += sh[i];
    var *= (1.0f / (D_MODEL - 1));

    const float a = alpha[0], b = beta[0];
    const float inv = a / (sqrtf(var) + 1e-6f);
    float4 o;
    o.x = dx * inv + b; o.y = dy * inv + b;
    o.z = dz * inv + b; o.w = dw * inv + b;
    yr[tid] = o;
}

// ---------------------------------------------------------------------------
// TF32 GEMM: C = A[M,K] @ BT[N,K]^T + bias (+relu) (+residual)
// BM=128 BN=128 BK=32, 128 threads (4 warps, 64x64 warp tiles), 2 CTAs/SM,
// 3-stage cp.async, 1 barrier/k-tile, BOTH operands via ldmatrix.x4.
// QKV mode (C1 != nullptr): Q,K outputs bf16; V output fp32 (ld = 1024).
// ---------------------------------------------------------------------------
#define ASTR 36
#define TILE_F (128 * ASTR)          // 4608 floats per operand tile
#define STG_F  (2 * TILE_F)          // 9216 floats per stage
#define MM_SMEM (3 * STG_F * 4)      // 110592 B

template<bool RELU, bool RES>
__global__ __launch_bounds__(128, 2) void mm_tf32(
    const float* __restrict__ A, const float* __restrict__ BT,
    const float* __restrict__ bias, const float* __restrict__ Rsd,
    float* __restrict__ C0, float* __restrict__ C1, float* __restrict__ C2,
    int M, int N, int K)
{
    extern __shared__ float smg[];

    const int tid  = threadIdx.x;
    const int warp = tid >> 5, lane = tid & 31;
    const int r = lane >> 2, c = lane & 3;
    const int wm = (warp >> 1) * 64, wn = (warp & 1) * 64;
    const int m0 = blockIdx.y * 128, n0 = blockIdx.x * 128;

    const uint32_t s0 = smem_u32(smg);

    // ldmatrix lane addressing (shared by A and B tiles, stride ASTR)
    const int g2 = lane >> 3, rowin = lane & 7;
    const uint32_t lLane =
        (uint32_t)((((g2 & 1) * 8 + rowin) * ASTR + (g2 >> 1) * 4) * 4);

    float acc[4][8][4];
#pragma unroll
    for (int i = 0; i < 4; i++)
#pragma unroll
        for (int j = 0; j < 8; j++)
#pragma unroll
            for (int k = 0; k < 4; k++) acc[i][j][k] = 0.f;

    const int NK = K >> 5;

    // k-tile load: A 128x32 (1024 chunks) + B 128x32 (1024 chunks), 128 thr
    auto load_tile = [&](int kt, int st) {
        const uint32_t ab = s0 + (uint32_t)(st * STG_F) * 4u;
        const uint32_t bb = ab + (uint32_t)TILE_F * 4u;
#pragma unroll
        for (int i = 0; i < 8; i++) {
            const int id = tid + 128 * i;
            const int row = id >> 3, kc = id & 7;
            const uint32_t off = (uint32_t)(row * ASTR + kc * 4) * 4u;
            CP_ASYNC16(ab + off, A  + (size_t)(m0 + row) * K + kt * 32 + kc * 4);
            CP_ASYNC16(bb + off, BT + (size_t)(n0 + row) * K + kt * 32 + kc * 4);
        }
    };

    load_tile(0, 0);
    CP_COMMIT();
    load_tile(1, 1);
    CP_COMMIT();

    for (int kt = 0; kt < NK; kt++) {
        const int st = kt - (kt / 3) * 3;
        CP_WAIT(1);
        __syncthreads();
        if (kt + 2 < NK) {
            const int s2 = (kt + 2) - ((kt + 2) / 3) * 3;
            load_tile(kt + 2, s2);
        }
        CP_COMMIT();

        const uint32_t aWarp = s0 + (uint32_t)(st * STG_F + wm * ASTR) * 4u + lLane;
        const uint32_t bWarp = s0 + (uint32_t)(st * STG_F + TILE_F + wn * ASTR) * 4u + lLane;

#pragma unroll
        for (int ks = 0; ks < 4; ks++) {
            uint32_t a[4][4], b[4][4];
#pragma unroll
            for (int fm = 0; fm < 4; fm++)
                ldsm_x4(a[fm], aWarp + (uint32_t)((fm * 16 * ASTR + ks * 8) * 4));
#pragma unroll
            for (int fp = 0; fp < 4; fp++)
                ldsm_x4(b[fp], bWarp + (uint32_t)((fp * 16 * ASTR + ks * 8) * 4));
            // b[fp]: reg0=(n0..7,k0..3) reg1=(n8..15,k0..3)
            //        reg2=(n0..7,k4..7) reg3=(n8..15,k4..7)
#pragma unroll
            for (int fm = 0; fm < 4; fm++)
#pragma unroll
                for (int fp = 0; fp < 4; fp++) {
                    mma_tf32(acc[fm][2 * fp + 0], a[fm], b[fp][0], b[fp][2]);
                    mma_tf32(acc[fm][2 * fp + 1], a[fm], b[fp][1], b[fp][3]);
                }
        }
    }

    if (C1 != nullptr) {
        // QKV mode: sel 0/1 -> bf16 Q/K; sel 2 -> fp32 V. ld = 1024.
        const int sel = n0 >> 10;
        const int nl0 = n0 & 1023;
        if (sel < 2) {
            __nv_bfloat16* Cb = (__nv_bfloat16*)(sel == 0 ? (void*)C0 : (void*)C1);
#pragma unroll
            for (int fm = 0; fm < 4; fm++) {
                const int row0 = m0 + wm + fm * 16 + r;
                const int row1 = row0 + 8;
#pragma unroll
                for (int fn = 0; fn < 8; fn++) {
                    const int colg = n0 + wn + fn * 8 + 2 * c;
                    const int col  = nl0 + wn + fn * 8 + 2 * c;
                    float2 bi = *(const float2*)&bias[colg];
                    uint32_t p0 = pack_bf16(acc[fm][fn][0] + bi.x, acc[fm][fn][1] + bi.y);
                    uint32_t p1 = pack_bf16(acc[fm][fn][2] + bi.x, acc[fm][fn][3] + bi.y);
                    *(uint32_t*)&Cb[(size_t)row0 * 1024 + col] = p0;
                    *(uint32_t*)&Cb[(size_t)row1 * 1024 + col] = p1;
                }
            }
        } else {
#pragma unroll
            for (int fm = 0; fm < 4; fm++) {
                const int row0 = m0 + wm + fm * 16 + r;
                const int row1 = row0 + 8;
#pragma unroll
                for (int fn = 0; fn < 8; fn++) {
                    const int colg = n0 + wn + fn * 8 + 2 * c;
                    const int col  = nl0 + wn + fn * 8 + 2 * c;
                    float2 bi = *(const float2*)&bias[colg];
                    *(float2*)&C2[(size_t)row0 * 1024 + col] =
                        make_float2(acc[fm][fn][0] + bi.x, acc[fm][fn][1] + bi.y);
                    *(float2*)&C2[(size_t)row1 * 1024 + col] =
                        make_float2(acc[fm][fn][2] + bi.x, acc[fm][fn][3] + bi.y);
                }
            }
        }
        return;
    }

#pragma unroll
    for (int fm = 0; fm < 4; fm++) {
        const int row0 = m0 + wm + fm * 16 + r;
        const int row1 = row0 + 8;
#pragma unroll
        for (int fn = 0; fn < 8; fn++) {
            const int col = n0 + wn + fn * 8 + 2 * c;
            float2 bi = *(const float2*)&bias[col];
            float v0 = acc[fm][fn][0] + bi.x;
            float v1 = acc[fm][fn][1] + bi.y;
            float v2 = acc[fm][fn][2] + bi.x;
            float v3 = acc[fm][fn][3] + bi.y;
            if (RELU) {
                v0 = fmaxf(v0, 0.f); v1 = fmaxf(v1, 0.f);
                v2 = fmaxf(v2, 0.f); v3 = fmaxf(v3, 0.f);
            }
            if (RES) {
                float2 r0 = *(const float2*)&Rsd[(size_t)row0 * N + col];
                float2 r1 = *(const float2*)&Rsd[(size_t)row1 * N + col];
                v0 += r0.x; v1 += r0.y; v2 += r1.x; v3 += r1.y;
            }
            *(float2*)&C0[(size_t)row0 * N + col] = make_float2(v0, v1);
            *(float2*)&C0[(size_t)row1 * N + col] = make_float2(v2, v3);
        }
    }
}

// ---------------------------------------------------------------------------
// Flash attention, bf16 m16n8k16. grid = (S/128, H), 128 threads, 2 CTAs/SM.
// (unchanged from R9)
// ---------------------------------------------------------------------------
#define ASTRU 36
#define QTILE_U (128 * ASTRU)
#define KTILE_U (64 * ASTRU)
#define ATT_SMEM ((QTILE_U + 4 * KTILE_U) * 4)
#define QK_SCALE 0.1803368801111364f       // 0.125 * log2(e)

__global__ __launch_bounds__(128, 2) void attn_bf16(
    const __nv_bfloat16* __restrict__ Qm, const __nv_bfloat16* __restrict__ Km,
    const __nv_bfloat16* __restrict__ Vt, float* __restrict__ Ctx)
{
    extern __shared__ uint32_t su[];
    uint32_t* Qs = su;                     // [128][36]
    uint32_t* Ks = Qs + QTILE_U;           // [2][64][36]
    uint32_t* Vs = Ks + 2 * KTILE_U;       // [2][64][36]

    const int tid  = threadIdx.x;
    const int warp = tid >> 5, lane = tid & 31;
    const int r = lane >> 2, c = lane & 3;
    const int wr = warp * 32;
    const int qb = blockIdx.x, h = blockIdx.y;
    const int cb = h * DK;

    const uint32_t qdst = smem_u32(Qs);
    const uint32_t kdst = smem_u32(Ks);
    const uint32_t vdst = smem_u32(Vs);

    const int g2 = lane >> 3, rowin = lane & 7;
    const uint32_t qLane = (uint32_t)(((g2 & 1) * 8 + rowin) * ASTRU + (g2 >> 1) * 4) * 4u;
    const uint32_t kLane = (uint32_t)(rowin * ASTRU + (g2 & 1) * 4) * 4u;

#pragma unroll
    for (int i = 0; i < 8; i++) {
        int id = tid + 128 * i;
        int row = id >> 3, ch = id & 7;
        CP_ASYNC16(qdst + (uint32_t)(row * ASTRU + ch * 4) * 4u,
                   Qm + (size_t)(qb * 128 + row) * D_MODEL + cb + ch * 8);
    }
#pragma unroll
    for (int i = 0; i < 4; i++) {
        int id = tid + 128 * i;
        int row = id >> 3, ch = id & 7;
        CP_ASYNC16(kdst + (uint32_t)(row * ASTRU + ch * 4) * 4u,
                   Km + (size_t)row * D_MODEL + cb + ch * 8);
        CP_ASYNC16(vdst + (uint32_t)(row * ASTRU + ch * 4) * 4u,
                   Vt + (size_t)(cb + row) * S_LEN + ch * 8);
    }
    CP_COMMIT();
    CP_WAIT(0);
    __syncthreads();

    const uint32_t qWarp = qdst + (uint32_t)(wr * ASTRU) * 4u + qLane;

    float mrow[2][2] = {{-1e30f, -1e30f}, {-1e30f, -1e30f}};
    float lrow[2][2] = {{0.f, 0.f}, {0.f, 0.f}};
    float acc[2][8][4];
#pragma unroll
    for (int i = 0; i < 2; i++)
#pragma unroll
        for (int j = 0; j < 8; j++)
#pragma unroll
            for (int k = 0; k < 4; k++) acc[i][j][k] = 0.f;

    for (int kt = 0; kt < S_LEN / 64; kt++) {
        const int buf = kt & 1;

        if (kt > 0) {
            CP_WAIT(0);
            __syncthreads();
        }
        if (kt + 1 < S_LEN / 64) {
            const int nb = buf ^ 1;
#pragma unroll
            for (int i = 0; i < 4; i++) {
                int id = tid + 128 * i;
                int row = id >> 3, ch = id & 7;
                CP_ASYNC16(kdst + (uint32_t)(nb * KTILE_U + row * ASTRU + ch * 4) * 4u,
                           Km + (size_t)((kt + 1) * 64 + row) * D_MODEL + cb + ch * 8);
                CP_ASYNC16(vdst + (uint32_t)(nb * KTILE_U + row * ASTRU + ch * 4) * 4u,
                           Vt + (size_t)(cb + row) * S_LEN + (kt + 1) * 64 + ch * 8);
            }
            CP_COMMIT();
        }

        float s[2][8][4];
#pragma unroll
        for (int i = 0; i < 2; i++)
#pragma unroll
            for (int j = 0; j < 8; j++)
#pragma unroll
                for (int k = 0; k < 4; k++) s[i][j][k] = 0.f;

        const uint32_t kTile = kdst + (uint32_t)(buf * KTILE_U) * 4u + kLane;
#pragma unroll
        for (int ks = 0; ks < 4; ks++) {
            uint32_t qf0[4], qf1[4];
            ldsm_x4(qf0, qWarp + (uint32_t)((ks * 8) * 4));
            ldsm_x4(qf1, qWarp + (uint32_t)((16 * ASTRU + ks * 8) * 4));
#pragma unroll
            for (int fn = 0; fn < 8; fn++) {
                uint32_t b0, b1;
                ldsm_x2(b0, b1, kTile + (uint32_t)((8 * fn * ASTRU + ks * 8) * 4));
                mma_bf16(s[0][fn], qf0, b0, b1);
                mma_bf16(s[1][fn], qf1, b0, b1);
            }
        }

        uint32_t pa[2][4][4];
#pragma unroll
        for (int fm = 0; fm < 2; fm++) {
            float mx0 = -1e30f, mx1 = -1e30f;
#pragma unroll
            for (int fn = 0; fn < 8; fn++) {
                mx0 = fmaxf(mx0, fmaxf(s[fm][fn][0], s[fm][fn][1]));
                mx1 = fmaxf(mx1, fmaxf(s[fm][fn][2], s[fm][fn][3]));
            }
            mx0 = fmaxf(mx0, __shfl_xor_sync(0xffffffffu, mx0, 1));
            mx0 = fmaxf(mx0, __shfl_xor_sync(0xffffffffu, mx0, 2));
            mx1 = fmaxf(mx1, __shfl_xor_sync(0xffffffffu, mx1, 1));
            mx1 = fmaxf(mx1, __shfl_xor_sync(0xffffffffu, mx1, 2));

            const float mn0 = fmaxf(mrow[fm][0], mx0);
            const float mn1 = fmaxf(mrow[fm][1], mx1);
            const float emn0 = mn0 * QK_SCALE;
            const float emn1 = mn1 * QK_SCALE;
            const float sc0 = ex2(fmaf(mrow[fm][0], QK_SCALE, -emn0));
            const float sc1 = ex2(fmaf(mrow[fm][1], QK_SCALE, -emn1));
            float ls0 = 0.f, ls1 = 0.f;
#pragma unroll
            for (int fn = 0; fn < 8; fn++) {
                float e0 = ex2(fmaf(s[fm][fn][0], QK_SCALE, -emn0));
                float e1 = ex2(fmaf(s[fm][fn][1], QK_SCALE, -emn0));
                float e2 = ex2(fmaf(s[fm][fn][2], QK_SCALE, -emn1));
                float e3 = ex2(fmaf(s[fm][fn][3], QK_SCALE, -emn1));
                ls0 += e0 + e1;
                ls1 += e2 + e3;
                pa[fm][fn >> 1][(fn & 1) * 2 + 0] = pack_bf16(e0, e1);
                pa[fm][fn >> 1][(fn & 1) * 2 + 1] = pack_bf16(e2, e3);
            }
            ls0 += __shfl_xor_sync(0xffffffffu, ls0, 1);
            ls0 += __shfl_xor_sync(0xffffffffu, ls0, 2);
            ls1 += __shfl_xor_sync(0xffffffffu, ls1, 1);
            ls1 += __shfl_xor_sync(0xffffffffu, ls1, 2);

            lrow[fm][0] = lrow[fm][0] * sc0 + ls0;
            lrow[fm][1] = lrow[fm][1] * sc1 + ls1;
            mrow[fm][0] = mn0; mrow[fm][1] = mn1;

#pragma unroll
            for (int fn = 0; fn < 8; fn++) {
                acc[fm][fn][0] *= sc0; acc[fm][fn][1] *= sc0;
                acc[fm][fn][2] *= sc1; acc[fm][fn][3] *= sc1;
            }
        }

        const uint32_t vTile = vdst + (uint32_t)(buf * KTILE_U) * 4u + kLane;
#pragma unroll
        for (int ks = 0; ks < 4; ks++) {
#pragma unroll
            for (int fn = 0; fn < 8; fn++) {
                uint32_t b0, b1;
                ldsm_x2(b0, b1, vTile + (uint32_t)((8 * fn * ASTRU + ks * 8) * 4));
                mma_bf16(acc[0][fn], pa[0][ks], b0, b1);
                mma_bf16(acc[1][fn], pa[1][ks], b0, b1);
            }
        }
    }

#pragma unroll
    for (int fm = 0; fm < 2; fm++) {
        const float inv0 = 1.f / lrow[fm][0];
        const float inv1 = 1.f / lrow[fm][1];
        const int row0 = qb * 128 + wr + fm * 16 + r;
        const int row1 = row0 + 8;
#pragma unroll
        for (int fn = 0; fn < 8; fn++) {
            const int col = cb + fn * 8 + 2 * c;
            *(float2*)&Ctx[(size_t)row0 * D_MODEL + col] =
                make_float2(acc[fm][fn][0] * inv0, acc[fm][fn][1] * inv0);
            *(float2*)&Ctx[(size_t)row1 * D_MODEL + col] =
                make_float2(acc[fm][fn][2] * inv1, acc[fm][fn][3] * inv1);
        }
    }
}

// ---------------------------------------------------------------------------
extern "C" void kernel_launch(void* const* d_in, const int* in_sizes, int n_in,
                              void* d_out, int out_size)
{
    const float* x    = (const float*)d_in[0];
    const float* Wq   = (const float*)d_in[1];
    const float* bq   = (const float*)d_in[2];
    const float* Wk   = (const float*)d_in[3];
    const float* bk   = (const float*)d_in[4];
    const float* Wv   = (const float*)d_in[5];
    const float* bv   = (const float*)d_in[6];
    const float* Wo   = (const float*)d_in[7];
    const float* bo   = (const float*)d_in[8];
    const float* ln1a = (const float*)d_in[9];
    const float* ln1b = (const float*)d_in[10];
    const float* W1   = (const float*)d_in[11];
    const float* b1   = (const float*)d_in[12];
    const float* W2   = (const float*)d_in[13];
    const float* b2   = (const float*)d_in[14];
    const float* ln2a = (const float*)d_in[15];
    const float* ln2b = (const float*)d_in[16];
    float* out = (float*)d_out;

    float *h1, *Vm, *ctx, *x1, *h2, *f1, *W3T, *WoT, *W1T, *W2T, *b3;
    __nv_bfloat16 *Qb, *Kb, *Vt;
    cudaGetSymbolAddress((void**)&h1,  g_h1);
    cudaGetSymbolAddress((void**)&Qb,  g_Qb);
    cudaGetSymbolAddress((void**)&Kb,  g_Kb);
    cudaGetSymbolAddress((void**)&Vm,  g_V);
    cudaGetSymbolAddress((void**)&Vt,  g_Vt);
    cudaGetSymbolAddress((void**)&ctx, g_ctx);
    cudaGetSymbolAddress((void**)&x1,  g_x1);
    cudaGetSymbolAddress((void**)&h2,  g_h2);
    cudaGetSymbolAddress((void**)&f1,  g_f1);
    cudaGetSymbolAddress((void**)&W3T, g_W3T);
    cudaGetSymbolAddress((void**)&WoT, g_WoT);
    cudaGetSymbolAddress((void**)&W1T, g_W1T);
    cudaGetSymbolAddress((void**)&W2T, g_W2T);
    cudaGetSymbolAddress((void**)&b3,  g_b3);

    cudaFuncSetAttribute(mm_tf32<false, false>,
                         cudaFuncAttributeMaxDynamicSharedMemorySize, MM_SMEM);
    cudaFuncSetAttribute(mm_tf32<false, true>,
                         cudaFuncAttributeMaxDynamicSharedMemorySize, MM_SMEM);
    cudaFuncSetAttribute(mm_tf32<true, false>,
                         cudaFuncAttributeMaxDynamicSharedMemorySize, MM_SMEM);
    cudaFuncSetAttribute(attn_bf16,
                         cudaFuncAttributeMaxDynamicSharedMemorySize, ATT_SMEM);

    // one-time weight transposes ([K,N] -> [N,K]) + bias concat
    transpose_k<<<dim3(D_MODEL / 32, D_MODEL / 32), 256>>>(Wq, W3T, D_MODEL, D_MODEL);
    transpose_k<<<dim3(D_MODEL / 32, D_MODEL / 32), 256>>>(Wk, W3T + 1024 * 1024, D_MODEL, D_MODEL);
    transpose_k<<<dim3(D_MODEL / 32, D_MODEL / 32), 256>>>(Wv, W3T + 2048 * 1024, D_MODEL, D_MODEL);
    transpose_k<<<dim3(D_MODEL / 32, D_MODEL / 32), 256>>>(Wo, WoT, D_MODEL, D_MODEL);
    transpose_k<<<dim3(D_FF   / 32, D_MODEL / 32), 256>>>(W1, W1T, D_MODEL, D_FF);
    transpose_k<<<dim3(D_MODEL / 32, D_FF   / 32), 256>>>(W2, W2T, D_FF, D_MODEL);
    biascat<<<(QKV_N + 255) / 256, 256>>>(bq, bk, bv, b3);

    const dim3 gQKV (QKV_N  / 128, S_LEN / 128);     // (24, 32)
    const dim3 gSmall(D_MODEL / 128, S_LEN / 128);   // (8, 32)
    const dim3 gFF1 (D_FF   / 128, S_LEN / 128);     // (32, 32)

    // residual 1
    ln_kernel<<<S_LEN, 256>>>(x, ln1a, ln1b, h1);
    mm_tf32<false, false><<<gQKV, 128, MM_SMEM>>>(h1, W3T, b3, nullptr,
        (float*)Qb, (float*)Kb, Vm, S_LEN, QKV_N, D_MODEL);
    vtrans<<<dim3(S_LEN / 64, D_MODEL / 32), 256>>>(Vm, Vt);
    attn_bf16<<<dim3(S_LEN / 128, NUM_HEADS), 128, ATT_SMEM>>>(Qb, Kb, Vt, ctx);
    mm_tf32<false, true><<<gSmall, 128, MM_SMEM>>>(ctx, WoT, bo, x,
        x1, nullptr, nullptr, S_LEN, D_MODEL, D_MODEL);

    // residual 2
    ln_kernel<<<S_LEN, 256>>>(x1, ln2a, ln2b, h2);
    mm_tf32<true,  false><<<gFF1, 128, MM_SMEM>>>(h2, W1T, b1, nullptr,
        f1, nullptr, nullptr, S_LEN, D_FF, D_MODEL);
    mm_tf32<false, true><<<gSmall, 128, MM_SMEM>>>(f1, W2T, b2, x1,
        out, nullptr, nullptr, S_LEN, D_MODEL, D_FF);
}

// round 12
// speedup vs baseline: 1.2292x; 1.2292x over previous
#include <cuda_runtime.h>
#include <cuda_bf16.h>
#include <math.h>
#include <stdint.h>

// ---------------------------------------------------------------------------
// Encoder layer: B=1, S=4096, D=1024, H=16, dk=64, F=4096, fp32 in/out.
// R12 = R9 base (905us) + bf16 QKV GEMM (h1/W3 bf16, m16n8k16), since the
// attention path already consumes bf16 and R8 showed its error is diluted.
// Other GEMMs: R9 tf32 mma.sync w/ ldmatrix A-frags. Attention: R9 bf16.
// ---------------------------------------------------------------------------

#define S_LEN 4096
#define D_MODEL 1024
#define D_FF 4096
#define NUM_HEADS 16
#define DK 64
#define QKV_N 3072

__device__ __nv_bfloat16 g_h1b[S_LEN * D_MODEL];
__device__ __nv_bfloat16 g_Qb[S_LEN * D_MODEL];
__device__ __nv_bfloat16 g_Kb[S_LEN * D_MODEL];
__device__ __nv_bfloat16 g_Vb[S_LEN * D_MODEL];
__device__ __nv_bfloat16 g_Vt[D_MODEL * S_LEN];   // [dim][key]
__device__ float g_ctx[S_LEN * D_MODEL];
__device__ float g_x1[S_LEN * D_MODEL];
__device__ float g_h2[S_LEN * D_MODEL];
__device__ float g_f1[S_LEN * D_FF];
__device__ uint32_t g_W3b[(D_MODEL / 2) * QKV_N];  // bf16 k-pair packed
__device__ float g_b3[QKV_N];

// ---------------------------------------------------------------------------
__device__ __forceinline__ void mma_tf32(float (&d)[4],
    const uint32_t (&a)[4], uint32_t b0, uint32_t b1)
{
    asm volatile(
        "mma.sync.aligned.m16n8k8.row.col.f32.tf32.tf32.f32 "
        "{%0,%1,%2,%3}, {%4,%5,%6,%7}, {%8,%9}, {%0,%1,%2,%3};\n"
        : "+f"(d[0]), "+f"(d[1]), "+f"(d[2]), "+f"(d[3])
        : "r"(a[0]), "r"(a[1]), "r"(a[2]), "r"(a[3]), "r"(b0), "r"(b1));
}
__device__ __forceinline__ void mma_bf16(float (&d)[4],
    const uint32_t (&a)[4], uint32_t b0, uint32_t b1)
{
    asm volatile(
        "mma.sync.aligned.m16n8k16.row.col.f32.bf16.bf16.f32 "
        "{%0,%1,%2,%3}, {%4,%5,%6,%7}, {%8,%9}, {%0,%1,%2,%3};\n"
        : "+f"(d[0]), "+f"(d[1]), "+f"(d[2]), "+f"(d[3])
        : "r"(a[0]), "r"(a[1]), "r"(a[2]), "r"(a[3]), "r"(b0), "r"(b1));
}
__device__ __forceinline__ void ldsm_x4(uint32_t (&d)[4], uint32_t saddr) {
    asm volatile("ldmatrix.sync.aligned.m8n8.x4.shared.b16 {%0,%1,%2,%3}, [%4];"
        : "=r"(d[0]), "=r"(d[1]), "=r"(d[2]), "=r"(d[3]) : "r"(saddr));
}
__device__ __forceinline__ void ldsm_x2(uint32_t& d0, uint32_t& d1, uint32_t saddr) {
    asm volatile("ldmatrix.sync.aligned.m8n8.x2.shared.b16 {%0,%1}, [%2];"
        : "=r"(d0), "=r"(d1) : "r"(saddr));
}
__device__ __forceinline__ uint32_t f2u(float x) { return __float_as_uint(x); }
__device__ __forceinline__ uint32_t smem_u32(const void* p) {
    return (uint32_t)__cvta_generic_to_shared(p);
}
__device__ __forceinline__ uint32_t pack_bf16(float lo, float hi) {
    __nv_bfloat162 v = __floats2bfloat162_rn(lo, hi);
    return *(uint32_t*)&v;
}
#define CP_ASYNC16(dst, src) \
    asm volatile("cp.async.cg.shared.global [%0], [%1], 16;\n" :: "r"(dst), "l"(src))
#define CP_COMMIT() asm volatile("cp.async.commit_group;\n")
#define CP_WAIT(n)  asm volatile("cp.async.wait_group %0;\n" :: "n"(n))

__device__ __forceinline__ float ex2(float x) {
    float y;
    asm("ex2.approx.f32 %0, %1;" : "=f"(y) : "f"(x));
    return y;
}

// ---------------------------------------------------------------------------
// Concat + pack Wq|Wk|Wv -> W3b [512 kpairs][3072] u32 (bf16 k-pairs), b3.
// ---------------------------------------------------------------------------
__global__ __launch_bounds__(256) void concat3b(
    const float* __restrict__ Wq, const float* __restrict__ Wk,
    const float* __restrict__ Wv, const float* __restrict__ bq,
    const float* __restrict__ bk, const float* __restrict__ bv,
    uint32_t* __restrict__ W3b, float* __restrict__ b3)
{
    const int idx = blockIdx.x * 256 + threadIdx.x;   // 512*3072 total
    const int kp = idx / QKV_N, n = idx % QKV_N;
    const int sel = n >> 10, col = n & 1023;
    const float* W = sel == 0 ? Wq : (sel == 1 ? Wk : Wv);
    const float lo = W[(size_t)(2 * kp) * D_MODEL + col];
    const float hi = W[(size_t)(2 * kp + 1) * D_MODEL + col];
    W3b[(size_t)kp * QKV_N + n] = pack_bf16(lo, hi);
    if (idx < QKV_N) {
        const float* b = sel == 0 ? bq : (sel == 1 ? bk : bv);
        b3[idx] = b[col];
    }
}

// ---------------------------------------------------------------------------
// V [S,1024] bf16 -> Vt [1024,S] bf16 (transpose)
// ---------------------------------------------------------------------------
__global__ __launch_bounds__(256) void vtrans_b(
    const __nv_bfloat16* __restrict__ V, __nv_bfloat16* __restrict__ Vt)
{
    __shared__ float t[64][33];
    const int k0 = blockIdx.x * 64;
    const int d0 = blockIdx.y * 32;
    const int x = threadIdx.x & 31;
    const int y = threadIdx.x >> 5;
#pragma unroll
    for (int i = 0; i < 64; i += 8)
        t[y + i][x] = __bfloat162float(V[(size_t)(k0 + y + i) * D_MODEL + d0 + x]);
    __syncthreads();
    uint32_t* Vt32 = (uint32_t*)Vt;
#pragma unroll
    for (int p = 0; p < 4; p++) {
        const int d = y + 8 * p;
        const int j = x;
        uint32_t v = pack_bf16(t[2 * j][d], t[2 * j + 1][d]);
        Vt32[(size_t)(d0 + d) * (S_LEN / 2) + (k0 >> 1) + j] = v;
    }
}

// ---------------------------------------------------------------------------
// LayerNorm (unbiased var ddof=1, denom = sqrt(var)+eps). OUT_BF16 variant
// packs to bf16 pairs.
// ---------------------------------------------------------------------------
template<bool OUT_BF16>
__global__ __launch_bounds__(256) void ln_kernel(
    const float* __restrict__ x, const float* __restrict__ alpha,
    const float* __restrict__ beta, void* __restrict__ yv)
{
    const int row = blockIdx.x;
    const float4* xr = (const float4*)(x + (size_t)row * D_MODEL);
    const int tid = threadIdx.x;

    float4 xl = xr[tid];
    float s = xl.x + xl.y + xl.z + xl.w;

    __shared__ float sh[8];
#pragma unroll
    for (int o = 16; o > 0; o >>= 1) s += __shfl_xor_sync(0xffffffffu, s, o);
    if ((tid & 31) == 0) sh[tid >> 5] = s;
    __syncthreads();
    float mu = 0.f;
#pragma unroll
    for (int i = 0; i < 8; i++) mu += sh[i];
    mu *= (1.0f / D_MODEL);
    __syncthreads();

    float dx = xl.x - mu, dy = xl.y - mu, dz = xl.z - mu, dw = xl.w - mu;
    float v = dx * dx + dy * dy + dz * dz + dw * dw;
#pragma unroll
    for (int o = 16; o > 0; o >>= 1) v += __shfl_xor_sync(0xffffffffu, v, o);
    if ((tid & 31) == 0) sh[tid >> 5] = v;
    __syncthreads();
    float var = 0.f;
#pragma unroll
    for (int i = 0; i < 8; i++) var += sh[i];
    var *= (1.0f / (D_MODEL - 1));

    const float a = alpha[0], b = beta[0];
    const float inv = a / (sqrtf(var) + 1e-6f);
    float ox = dx * inv + b, oy = dy * inv + b;
    float oz = dz * inv + b, ow = dw * inv + b;
    if (OUT_BF16) {
        uint32_t* yr = (uint32_t*)yv + (size_t)row * (D_MODEL / 2);
        yr[2 * tid + 0] = pack_bf16(ox, oy);
        yr[2 * tid + 1] = pack_bf16(oz, ow);
    } else {
        float4* yr = (float4*)yv + (size_t)row * (D_MODEL / 4);
        yr[tid] = make_float4(ox, oy, oz, ow);
    }
}

// ---------------------------------------------------------------------------
// TF32 GEMM (R9): C = A[M,K] @ W[K,N] + bias (+relu) (+residual)
// BM=128 BN=128 BK=32, 256 threads, 3-stage cp.async, 1 barrier/k-tile,
// 2 CTAs/SM, ldmatrix A-frags.
// ---------------------------------------------------------------------------
#define ASTR 36
#define BSTR 136
#define A_TILE (128 * ASTR)
#define B_TILE (32 * BSTR)
#define STG_F  (A_TILE + B_TILE)
#define MM_SMEM (3 * STG_F * 4)

template<bool RELU, bool RES>
__global__ __launch_bounds__(256, 2) void mm_tf32(
    const float* __restrict__ A, const float* __restrict__ W,
    const float* __restrict__ bias, const float* __restrict__ Rsd,
    float* __restrict__ C, int M, int N, int K)
{
    extern __shared__ float smg[];

    const int tid  = threadIdx.x;
    const int warp = tid >> 5, lane = tid & 31;
    const int r = lane >> 2, c = lane & 3;
    const int wm = (warp >> 2) * 64, wn = (warp & 3) * 32;
    const int m0 = blockIdx.y * 128, n0 = blockIdx.x * 128;

    const uint32_t s0 = smem_u32(smg);

    const int g2 = lane >> 3, rowin = lane & 7;
    const uint32_t aLane = (uint32_t)((((g2 & 1) * 8 + rowin) * ASTR + (g2 >> 1) * 4) * 4);

    float acc[4][4][4];
#pragma unroll
    for (int i = 0; i < 4; i++)
#pragma unroll
        for (int j = 0; j < 4; j++)
#pragma unroll
            for (int k = 0; k < 4; k++) acc[i][j][k] = 0.f;

    const int NK = K >> 5;

    auto load_tile = [&](int kt, int st) {
        const uint32_t ab = s0 + (uint32_t)(st * STG_F) * 4u;
        const uint32_t bb = ab + (uint32_t)A_TILE * 4u;
#pragma unroll
        for (int i = 0; i < 4; i++) {
            const int id = tid + 256 * i;
            const int ar = id >> 3, akc = id & 7;
            CP_ASYNC16(ab + (uint32_t)(ar * ASTR + akc * 4) * 4u,
                       A + (size_t)(m0 + ar) * K + kt * 32 + akc * 4);
            const int br = id >> 5, bnc = id & 31;
            CP_ASYNC16(bb + (uint32_t)(br * BSTR + bnc * 4) * 4u,
                       W + (size_t)(kt * 32 + br) * N + n0 + bnc * 4);
        }
    };

    load_tile(0, 0);
    CP_COMMIT();
    load_tile(1, 1);
    CP_COMMIT();

    for (int kt = 0; kt < NK; kt++) {
        const int st = kt - (kt / 3) * 3;
        CP_WAIT(1);
        __syncthreads();
        if (kt + 2 < NK) {
            const int s2 = (kt + 2) - ((kt + 2) / 3) * 3;
            load_tile(kt + 2, s2);
        }
        CP_COMMIT();

        const uint32_t aWarp = s0 + (uint32_t)(st * STG_F + wm * ASTR) * 4u + aLane;
        const float* Bb = smg + st * STG_F + A_TILE;
#pragma unroll
        for (int ks = 0; ks < 4; ks++) {
            uint32_t a[4][4], b[4][2];
#pragma unroll
            for (int fm = 0; fm < 4; fm++)
                ldsm_x4(a[fm], aWarp + (uint32_t)((fm * 16 * ASTR + ks * 8) * 4));
#pragma unroll
            for (int fn = 0; fn < 4; fn++) {
                const float* q = Bb + (ks * 8 + c) * BSTR + wn + fn * 8 + r;
                b[fn][0] = f2u(q[0]);
                b[fn][1] = f2u(q[4 * BSTR]);
            }
#pragma unroll
            for (int fm = 0; fm < 4; fm++)
#pragma unroll
                for (int fn = 0; fn < 4; fn++)
                    mma_tf32(acc[fm][fn], a[fm], b[fn][0], b[fn][1]);
        }
    }

#pragma unroll
    for (int fm = 0; fm < 4; fm++) {
        const int row0 = m0 + wm + fm * 16 + r;
        const int row1 = row0 + 8;
#pragma unroll
        for (int fn = 0; fn < 4; fn++) {
            const int col = n0 + wn + fn * 8 + 2 * c;
            float2 bi = *(const float2*)&bias[col];
            float v0 = acc[fm][fn][0] + bi.x;
            float v1 = acc[fm][fn][1] + bi.y;
            float v2 = acc[fm][fn][2] + bi.x;
            float v3 = acc[fm][fn][3] + bi.y;
            if (RELU) {
                v0 = fmaxf(v0, 0.f); v1 = fmaxf(v1, 0.f);
                v2 = fmaxf(v2, 0.f); v3 = fmaxf(v3, 0.f);
            }
            if (RES) {
                float2 r0 = *(const float2*)&Rsd[(size_t)row0 * N + col];
                float2 r1 = *(const float2*)&Rsd[(size_t)row1 * N + col];
                v0 += r0.x; v1 += r0.y; v2 += r1.x; v3 += r1.y;
            }
            *(float2*)&C[(size_t)row0 * N + col] = make_float2(v0, v1);
            *(float2*)&C[(size_t)row1 * N + col] = make_float2(v2, v3);
        }
    }
}

// ---------------------------------------------------------------------------
// BF16 QKV GEMM: [Q|K|V](bf16) = h1b[M,K](bf16) @ W3b + b3.
// BM=128 BN=128 BK=32 (16 u32 kpairs), 256 threads, 8 warps (64x32 tiles),
// 3-stage cp.async, 2 CTAs/SM. A-frags via ldmatrix.x4 (u32 kpair space);
// B-frags scalar u32 (same addressing as tf32, rows = kpairs).
// ---------------------------------------------------------------------------
#define QASTR 36                      // u32: 16 data + pad? (32 bf16 = 16 u32) + 20 pad -> keep 36 for ldsm CF
#define QBSTR 136                     // u32 row stride for B (128 data + 8)
#define QA_TILE (128 * QASTR)
#define QB_TILE (16 * QBSTR)
#define QSTG_U  (QA_TILE + QB_TILE)
#define QKV_SMEM (3 * QSTG_U * 4)

__global__ __launch_bounds__(256, 2) void mm_qkv_bf16(
    const uint32_t* __restrict__ A,    // h1b as u32 [M][512]
    const uint32_t* __restrict__ W3b,  // [512][3072]
    const float* __restrict__ bias,
    __nv_bfloat16* __restrict__ Q, __nv_bfloat16* __restrict__ Kout,
    __nv_bfloat16* __restrict__ V)
{
    extern __shared__ uint32_t smq[];

    const int tid  = threadIdx.x;
    const int warp = tid >> 5, lane = tid & 31;
    const int r = lane >> 2, c = lane & 3;
    const int wm = (warp >> 2) * 64, wn = (warp & 3) * 32;
    const int m0 = blockIdx.y * 128, n0 = blockIdx.x * 128;
    const int KU = D_MODEL / 2;       // 512 kpairs

    const uint32_t s0 = smem_u32(smq);
    const int g2 = lane >> 3, rowin = lane & 7;
    const uint32_t aLane = (uint32_t)(((g2 & 1) * 8 + rowin) * QASTR + (g2 >> 1) * 4) * 4u;

    float acc[4][4][4];
#pragma unroll
    for (int i = 0; i < 4; i++)
#pragma unroll
        for (int j = 0; j < 4; j++)
#pragma unroll
            for (int k = 0; k < 4; k++) acc[i][j][k] = 0.f;

    const int NK = 32;   // 1024 / 32

    // per k-tile: A 128 rows x 16 u32 (512 chunks) + B 16 rows x 128 u32 (512)
    auto load_tile = [&](int kt, int st) {
        const uint32_t ab = s0 + (uint32_t)(st * QSTG_U) * 4u;
        const uint32_t bb = ab + (uint32_t)QA_TILE * 4u;
#pragma unroll
        for (int i = 0; i < 2; i++) {
            const int id = tid + 256 * i;
            const int ar = id >> 2, akc = id & 3;
            CP_ASYNC16(ab + (uint32_t)(ar * QASTR + akc * 4) * 4u,
                       A + (size_t)(m0 + ar) * KU + kt * 16 + akc * 4);
            const int br = id >> 5, bnc = id & 31;
            CP_ASYNC16(bb + (uint32_t)(br * QBSTR + bnc * 4) * 4u,
                       W3b + (size_t)(kt * 16 + br) * QKV_N + n0 + bnc * 4);
        }
    };

    load_tile(0, 0);
    CP_COMMIT();
    load_tile(1, 1);
    CP_COMMIT();

    for (int kt = 0; kt < NK; kt++) {
        const int st = kt - (kt / 3) * 3;
        CP_WAIT(1);
        __syncthreads();
        if (kt + 2 < NK) {
            const int s2 = (kt + 2) - ((kt + 2) / 3) * 3;
            load_tile(kt + 2, s2);
        }
        CP_COMMIT();

        const uint32_t aWarp = s0 + (uint32_t)(st * QSTG_U + wm * QASTR) * 4u + aLane;
        const uint32_t* Bb = smq + st * QSTG_U + QA_TILE;
#pragma unroll
        for (int ks = 0; ks < 2; ks++) {      // 2 x k16
            uint32_t a[4][4], b[4][2];
#pragma unroll
            for (int fm = 0; fm < 4; fm++)
                ldsm_x4(a[fm], aWarp + (uint32_t)((fm * 16 * QASTR + ks * 8) * 4));
#pragma unroll
            for (int fn = 0; fn < 4; fn++) {
                const uint32_t* q = Bb + (ks * 8 + c) * QBSTR + wn + fn * 8 + r;
                b[fn][0] = q[0];
                b[fn][1] = q[4 * QBSTR];
            }
#pragma unroll
            for (int fm = 0; fm < 4; fm++)
#pragma unroll
                for (int fn = 0; fn < 4; fn++)
                    mma_bf16(acc[fm][fn], a[fm], b[fn][0], b[fn][1]);
        }
    }

    // epilogue: bf16 outputs (ld = 1024)
    const int sel = n0 >> 10;
    const int nl0 = n0 & 1023;
    __nv_bfloat16* Cb = sel == 0 ? Q : (sel == 1 ? Kout : V);
#pragma unroll
    for (int fm = 0; fm < 4; fm++) {
        const int row0 = m0 + wm + fm * 16 + r;
        const int row1 = row0 + 8;
#pragma unroll
        for (int fn = 0; fn < 4; fn++) {
            const int colg = n0 + wn + fn * 8 + 2 * c;
            const int col  = nl0 + wn + fn * 8 + 2 * c;
            float2 bi = *(const float2*)&bias[colg];
            *(uint32_t*)&Cb[(size_t)row0 * 1024 + col] =
                pack_bf16(acc[fm][fn][0] + bi.x, acc[fm][fn][1] + bi.y);
            *(uint32_t*)&Cb[(size_t)row1 * 1024 + col] =
                pack_bf16(acc[fm][fn][2] + bi.x, acc[fm][fn][3] + bi.y);
        }
    }
}

// ---------------------------------------------------------------------------
// Flash attention, bf16 m16n8k16. grid = (S/128, H), 128 threads, 2 CTAs/SM.
// (R9, unchanged)
// ---------------------------------------------------------------------------
#define ASTRU 36
#define QTILE_U (128 * ASTRU)
#define KTILE_U (64 * ASTRU)
#define ATT_SMEM ((QTILE_U + 4 * KTILE_U) * 4)
#define QK_SCALE 0.1803368801111364f       // 0.125 * log2(e)

__global__ __launch_bounds__(128, 2) void attn_bf16(
    const __nv_bfloat16* __restrict__ Qm, const __nv_bfloat16* __restrict__ Km,
    const __nv_bfloat16* __restrict__ Vt, float* __restrict__ Ctx)
{
    extern __shared__ uint32_t su[];
    uint32_t* Qs = su;
    uint32_t* Ks = Qs + QTILE_U;
    uint32_t* Vs = Ks + 2 * KTILE_U;

    const int tid  = threadIdx.x;
    const int warp = tid >> 5, lane = tid & 31;
    const int r = lane >> 2, c = lane & 3;
    const int wr = warp * 32;
    const int qb = blockIdx.x, h = blockIdx.y;
    const int cb = h * DK;

    const uint32_t qdst = smem_u32(Qs);
    const uint32_t kdst = smem_u32(Ks);
    const uint32_t vdst = smem_u32(Vs);

    const int g2 = lane >> 3, rowin = lane & 7;
    const uint32_t qLane = (uint32_t)(((g2 & 1) * 8 + rowin) * ASTRU + (g2 >> 1) * 4) * 4u;
    const uint32_t kLane = (uint32_t)(rowin * ASTRU + (g2 & 1) * 4) * 4u;

#pragma unroll
    for (int i = 0; i < 8; i++) {
        int id = tid + 128 * i;
        int row = id >> 3, ch = id & 7;
        CP_ASYNC16(qdst + (uint32_t)(row * ASTRU + ch * 4) * 4u,
                   Qm + (size_t)(qb * 128 + row) * D_MODEL + cb + ch * 8);
    }
#pragma unroll
    for (int i = 0; i < 4; i++) {
        int id = tid + 128 * i;
        int row = id >> 3, ch = id & 7;
        CP_ASYNC16(kdst + (uint32_t)(row * ASTRU + ch * 4) * 4u,
                   Km + (size_t)row * D_MODEL + cb + ch * 8);
        CP_ASYNC16(vdst + (uint32_t)(row * ASTRU + ch * 4) * 4u,
                   Vt + (size_t)(cb + row) * S_LEN + ch * 8);
    }
    CP_COMMIT();
    CP_WAIT(0);
    __syncthreads();

    const uint32_t qWarp = qdst + (uint32_t)(wr * ASTRU) * 4u + qLane;

    float mrow[2][2] = {{-1e30f, -1e30f}, {-1e30f, -1e30f}};
    float lrow[2][2] = {{0.f, 0.f}, {0.f, 0.f}};
    float acc[2][8][4];
#pragma unroll
    for (int i = 0; i < 2; i++)
#pragma unroll
        for (int j = 0; j < 8; j++)
#pragma unroll
            for (int k = 0; k < 4; k++) acc[i][j][k] = 0.f;

    for (int kt = 0; kt < S_LEN / 64; kt++) {
        const int buf = kt & 1;

        if (kt > 0) {
            CP_WAIT(0);
            __syncthreads();
        }
        if (kt + 1 < S_LEN / 64) {
            const int nb = buf ^ 1;
#pragma unroll
            for (int i = 0; i < 4; i++) {
                int id = tid + 128 * i;
                int row = id >> 3, ch = id & 7;
                CP_ASYNC16(kdst + (uint32_t)(nb * KTILE_U + row * ASTRU + ch * 4) * 4u,
                           Km + (size_t)((kt + 1) * 64 + row) * D_MODEL + cb + ch * 8);
                CP_ASYNC16(vdst + (uint32_t)(nb * KTILE_U + row * ASTRU + ch * 4) * 4u,
                           Vt + (size_t)(cb + row) * S_LEN + (kt + 1) * 64 + ch * 8);
            }
            CP_COMMIT();
        }

        float s[2][8][4];
#pragma unroll
        for (int i = 0; i < 2; i++)
#pragma unroll
            for (int j = 0; j < 8; j++)
#pragma unroll
                for (int k = 0; k < 4; k++) s[i][j][k] = 0.f;

        const uint32_t kTile = kdst + (uint32_t)(buf * KTILE_U) * 4u + kLane;
#pragma unroll
        for (int ks = 0; ks < 4; ks++) {
            uint32_t qf0[4], qf1[4];
            ldsm_x4(qf0, qWarp + (uint32_t)((ks * 8) * 4));
            ldsm_x4(qf1, qWarp + (uint32_t)((16 * ASTRU + ks * 8) * 4));
#pragma unroll
            for (int fn = 0; fn < 8; fn++) {
                uint32_t b0, b1;
                ldsm_x2(b0, b1, kTile + (uint32_t)((8 * fn * ASTRU + ks * 8) * 4));
                mma_bf16(s[0][fn], qf0, b0, b1);
                mma_bf16(s[1][fn], qf1, b0, b1);
            }
        }

        uint32_t pa[2][4][4];
#pragma unroll
        for (int fm = 0; fm < 2; fm++) {
            float mx0 = -1e30f, mx1 = -1e30f;
#pragma unroll
            for (int fn = 0; fn < 8; fn++) {
                mx0 = fmaxf(mx0, fmaxf(s[fm][fn][0], s[fm][fn][1]));
                mx1 = fmaxf(mx1, fmaxf(s[fm][fn][2], s[fm][fn][3]));
            }
            mx0 = fmaxf(mx0, __shfl_xor_sync(0xffffffffu, mx0, 1));
            mx0 = fmaxf(mx0, __shfl_xor_sync(0xffffffffu, mx0, 2));
            mx1 = fmaxf(mx1, __shfl_xor_sync(0xffffffffu, mx1, 1));
            mx1 = fmaxf(mx1, __shfl_xor_sync(0xffffffffu, mx1, 2));

            const float mn0 = fmaxf(mrow[fm][0], mx0);
            const float mn1 = fmaxf(mrow[fm][1], mx1);
            const float emn0 = mn0 * QK_SCALE;
            const float emn1 = mn1 * QK_SCALE;
            const float sc0 = ex2(fmaf(mrow[fm][0], QK_SCALE, -emn0));
            const float sc1 = ex2(fmaf(mrow[fm][1], QK_SCALE, -emn1));
            float ls0 = 0.f, ls1 = 0.f;
#pragma unroll
            for (int fn = 0; fn < 8; fn++) {
                float e0 = ex2(fmaf(s[fm][fn][0], QK_SCALE, -emn0));
                float e1 = ex2(fmaf(s[fm][fn][1], QK_SCALE, -emn0));
                float e2 = ex2(fmaf(s[fm][fn][2], QK_SCALE, -emn1));
                float e3 = ex2(fmaf(s[fm][fn][3], QK_SCALE, -emn1));
                ls0 += e0 + e1;
                ls1 += e2 + e3;
                pa[fm][fn >> 1][(fn & 1) * 2 + 0] = pack_bf16(e0, e1);
                pa[fm][fn >> 1][(fn & 1) * 2 + 1] = pack_bf16(e2, e3);
            }
            ls0 += __shfl_xor_sync(0xffffffffu, ls0, 1);
            ls0 += __shfl_xor_sync(0xffffffffu, ls0, 2);
            ls1 += __shfl_xor_sync(0xffffffffu, ls1, 1);
            ls1 += __shfl_xor_sync(0xffffffffu, ls1, 2);

            lrow[fm][0] = lrow[fm][0] * sc0 + ls0;
            lrow[fm][1] = lrow[fm][1] * sc1 + ls1;
            mrow[fm][0] = mn0; mrow[fm][1] = mn1;

#pragma unroll
            for (int fn = 0; fn < 8; fn++) {
                acc[fm][fn][0] *= sc0; acc[fm][fn][1] *= sc0;
                acc[fm][fn][2] *= sc1; acc[fm][fn][3] *= sc1;
            }
        }

        const uint32_t vTile = vdst + (uint32_t)(buf * KTILE_U) * 4u + kLane;
#pragma unroll
        for (int ks = 0; ks < 4; ks++) {
#pragma unroll
            for (int fn = 0; fn < 8; fn++) {
                uint32_t b0, b1;
                ldsm_x2(b0, b1, vTile + (uint32_t)((8 * fn * ASTRU + ks * 8) * 4));
                mma_bf16(acc[0][fn], pa[0][ks], b0, b1);
                mma_bf16(acc[1][fn], pa[1][ks], b0, b1);
            }
        }
    }

#pragma unroll
    for (int fm = 0; fm < 2; fm++) {
        const float inv0 = 1.f / lrow[fm][0];
        const float inv1 = 1.f / lrow[fm][1];
        const int row0 = qb * 128 + wr + fm * 16 + r;
        const int row1 = row0 + 8;
#pragma unroll
        for (int fn = 0; fn < 8; fn++) {
            const int col = cb + fn * 8 + 2 * c;
            *(float2*)&Ctx[(size_t)row0 * D_MODEL + col] =
                make_float2(acc[fm][fn][0] * inv0, acc[fm][fn][1] * inv0);
            *(float2*)&Ctx[(size_t)row1 * D_MODEL + col] =
                make_float2(acc[fm][fn][2] * inv1, acc[fm][fn][3] * inv1);
        }
    }
}

// ---------------------------------------------------------------------------
extern "C" void kernel_launch(void* const* d_in, const int* in_sizes, int n_in,
                              void* d_out, int out_size)
{
    const float* x    = (const float*)d_in[0];
    const float* Wq   = (const float*)d_in[1];
    const float* bq   = (const float*)d_in[2];
    const float* Wk   = (const float*)d_in[3];
    const float* bk   = (const float*)d_in[4];
    const float* Wv   = (const float*)d_in[5];
    const float* bv   = (const float*)d_in[6];
    const float* Wo   = (const float*)d_in[7];
    const float* bo   = (const float*)d_in[8];
    const float* ln1a = (const float*)d_in[9];
    const float* ln1b = (const float*)d_in[10];
    const float* W1   = (const float*)d_in[11];
    const float* b1   = (const float*)d_in[12];
    const float* W2   = (const float*)d_in[13];
    const float* b2   = (const float*)d_in[14];
    const float* ln2a = (const float*)d_in[15];
    const float* ln2b = (const float*)d_in[16];
    float* out = (float*)d_out;

    float *ctx, *x1, *h2, *f1, *b3;
    __nv_bfloat16 *h1b, *Qb, *Kb, *Vb, *Vt;
    uint32_t *W3b;
    cudaGetSymbolAddress((void**)&h1b, g_h1b);
    cudaGetSymbolAddress((void**)&Qb,  g_Qb);
    cudaGetSymbolAddress((void**)&Kb,  g_Kb);
    cudaGetSymbolAddress((void**)&Vb,  g_Vb);
    cudaGetSymbolAddress((void**)&Vt,  g_Vt);
    cudaGetSymbolAddress((void**)&ctx, g_ctx);
    cudaGetSymbolAddress((void**)&x1,  g_x1);
    cudaGetSymbolAddress((void**)&h2,  g_h2);
    cudaGetSymbolAddress((void**)&f1,  g_f1);
    cudaGetSymbolAddress((void**)&W3b, g_W3b);
    cudaGetSymbolAddress((void**)&b3,  g_b3);

    cudaFuncSetAttribute(mm_tf32<false, false>,
                         cudaFuncAttributeMaxDynamicSharedMemorySize, MM_SMEM);
    cudaFuncSetAttribute(mm_tf32<false, true>,
                         cudaFuncAttributeMaxDynamicSharedMemorySize, MM_SMEM);
    cudaFuncSetAttribute(mm_tf32<true, false>,
                         cudaFuncAttributeMaxDynamicSharedMemorySize, MM_SMEM);
    cudaFuncSetAttribute(mm_qkv_bf16,
                         cudaFuncAttributeMaxDynamicSharedMemorySize, QKV_SMEM);
    cudaFuncSetAttribute(attn_bf16,
                         cudaFuncAttributeMaxDynamicSharedMemorySize, ATT_SMEM);

    concat3b<<<(D_MODEL / 2) * QKV_N / 256, 256>>>(Wq, Wk, Wv, bq, bk, bv, W3b, b3);

    const dim3 gQKV (QKV_N  / 128, S_LEN / 128);     // (24, 32)
    const dim3 gSmall(D_MODEL / 128, S_LEN / 128);   // (8, 32)
    const dim3 gFF1 (D_FF   / 128, S_LEN / 128);     // (32, 32)

    // residual 1
    ln_kernel<true><<<S_LEN, 256>>>(x, ln1a, ln1b, h1b);
    mm_qkv_bf16<<<gQKV, 256, QKV_SMEM>>>((const uint32_t*)h1b, W3b, b3, Qb, Kb, Vb);
    vtrans_b<<<dim3(S_LEN / 64, D_MODEL / 32), 256>>>(Vb, Vt);
    attn_bf16<<<dim3(S_LEN / 128, NUM_HEADS), 128, ATT_SMEM>>>(Qb, Kb, Vt, ctx);
    mm_tf32<false, true><<<gSmall, 256, MM_SMEM>>>(ctx, Wo, bo, x, x1, S_LEN, D_MODEL, D_MODEL);

    // residual 2
    ln_kernel<false><<<S_LEN, 256>>>(x1, ln2a, ln2b, h2);
    mm_tf32<true,  false><<<gFF1, 256, MM_SMEM>>>(h2, W1, b1, nullptr, f1, S_LEN, D_FF, D_MODEL);
    mm_tf32<false, true><<<gSmall, 256, MM_SMEM>>>(f1, W2, b2, x1, out, S_LEN, D_MODEL, D_FF);
}

// round 13
// speedup vs baseline: 1.5072x; 1.2261x over previous
#include <cuda_runtime.h>
#include <cuda_bf16.h>
#include <cuda_fp16.h>
#include <math.h>
#include <stdint.h>

// ---------------------------------------------------------------------------
// Encoder layer: B=1, S=4096, D=1024, H=16, dk=64, F=4096, fp32 in/out.
// R13: ALL GEMMs on 16-bit mma.m16n8k16. QKV in bf16 (R12, proven); Wo/FFN1/
// FFN2 in fp16 (same 10-bit mantissa as tf32 -> precision-equivalent, 2x
// throughput). Residual stream fp32. Attention: R9 bf16 flash kernel, now
// emitting fp16 ctx.
// ---------------------------------------------------------------------------

#define S_LEN 4096
#define D_MODEL 1024
#define D_FF 4096
#define NUM_HEADS 16
#define DK 64
#define QKV_N 3072

__device__ __nv_bfloat16 g_h1b[S_LEN * D_MODEL];
__device__ __nv_bfloat16 g_Qb[S_LEN * D_MODEL];
__device__ __nv_bfloat16 g_Kb[S_LEN * D_MODEL];
__device__ __nv_bfloat16 g_Vb[S_LEN * D_MODEL];
__device__ __nv_bfloat16 g_Vt[D_MODEL * S_LEN];    // [dim][key]
__device__ uint32_t g_ctxh[S_LEN * (D_MODEL / 2)]; // ctx fp16 pairs
__device__ float g_x1[S_LEN * D_MODEL];
__device__ uint32_t g_h2h[S_LEN * (D_MODEL / 2)];  // LN2 out fp16 pairs
__device__ uint32_t g_f1h[S_LEN * (D_FF / 2)];     // FFN1 out fp16 pairs
__device__ uint32_t g_W3b[(D_MODEL / 2) * QKV_N];  // bf16 k-pair packed
__device__ float g_b3[QKV_N];
__device__ uint32_t g_WoP[(D_MODEL / 2) * D_MODEL];
__device__ uint32_t g_W1P[(D_MODEL / 2) * D_FF];
__device__ uint32_t g_W2P[(D_FF / 2) * D_MODEL];

// ---------------------------------------------------------------------------
__device__ __forceinline__ void mma_bf16(float (&d)[4],
    const uint32_t (&a)[4], uint32_t b0, uint32_t b1)
{
    asm volatile(
        "mma.sync.aligned.m16n8k16.row.col.f32.bf16.bf16.f32 "
        "{%0,%1,%2,%3}, {%4,%5,%6,%7}, {%8,%9}, {%0,%1,%2,%3};\n"
        : "+f"(d[0]), "+f"(d[1]), "+f"(d[2]), "+f"(d[3])
        : "r"(a[0]), "r"(a[1]), "r"(a[2]), "r"(a[3]), "r"(b0), "r"(b1));
}
__device__ __forceinline__ void mma_f16(float (&d)[4],
    const uint32_t (&a)[4], uint32_t b0, uint32_t b1)
{
    asm volatile(
        "mma.sync.aligned.m16n8k16.row.col.f32.f16.f16.f32 "
        "{%0,%1,%2,%3}, {%4,%5,%6,%7}, {%8,%9}, {%0,%1,%2,%3};\n"
        : "+f"(d[0]), "+f"(d[1]), "+f"(d[2]), "+f"(d[3])
        : "r"(a[0]), "r"(a[1]), "r"(a[2]), "r"(a[3]), "r"(b0), "r"(b1));
}
__device__ __forceinline__ void ldsm_x4(uint32_t (&d)[4], uint32_t saddr) {
    asm volatile("ldmatrix.sync.aligned.m8n8.x4.shared.b16 {%0,%1,%2,%3}, [%4];"
        : "=r"(d[0]), "=r"(d[1]), "=r"(d[2]), "=r"(d[3]) : "r"(saddr));
}
__device__ __forceinline__ void ldsm_x2(uint32_t& d0, uint32_t& d1, uint32_t saddr) {
    asm volatile("ldmatrix.sync.aligned.m8n8.x2.shared.b16 {%0,%1}, [%2];"
        : "=r"(d0), "=r"(d1) : "r"(saddr));
}
__device__ __forceinline__ uint32_t smem_u32(const void* p) {
    return (uint32_t)__cvta_generic_to_shared(p);
}
__device__ __forceinline__ uint32_t pack_bf16(float lo, float hi) {
    __nv_bfloat162 v = __floats2bfloat162_rn(lo, hi);
    return *(uint32_t*)&v;
}
__device__ __forceinline__ uint32_t pack_f16(float lo, float hi) {
    __half2 v = __floats2half2_rn(lo, hi);
    return *(uint32_t*)&v;
}
#define CP_ASYNC16(dst, src) \
    asm volatile("cp.async.cg.shared.global [%0], [%1], 16;\n" :: "r"(dst), "l"(src))
#define CP_COMMIT() asm volatile("cp.async.commit_group;\n")
#define CP_WAIT(n)  asm volatile("cp.async.wait_group %0;\n" :: "n"(n))

__device__ __forceinline__ float ex2(float x) {
    float y;
    asm("ex2.approx.f32 %0, %1;" : "=f"(y) : "f"(x));
    return y;
}

// ---------------------------------------------------------------------------
// Concat + pack Wq|Wk|Wv -> W3b (bf16 k-pairs), b3
// ---------------------------------------------------------------------------
__global__ __launch_bounds__(256) void concat3b(
    const float* __restrict__ Wq, const float* __restrict__ Wk,
    const float* __restrict__ Wv, const float* __restrict__ bq,
    const float* __restrict__ bk, const float* __restrict__ bv,
    uint32_t* __restrict__ W3b, float* __restrict__ b3)
{
    const int idx = blockIdx.x * 256 + threadIdx.x;
    const int kp = idx / QKV_N, n = idx % QKV_N;
    const int sel = n >> 10, col = n & 1023;
    const float* W = sel == 0 ? Wq : (sel == 1 ? Wk : Wv);
    const float lo = W[(size_t)(2 * kp) * D_MODEL + col];
    const float hi = W[(size_t)(2 * kp + 1) * D_MODEL + col];
    W3b[(size_t)kp * QKV_N + n] = pack_bf16(lo, hi);
    if (idx < QKV_N) {
        const float* b = sel == 0 ? bq : (sel == 1 ? bk : bv);
        b3[idx] = b[col];
    }
}

// Pack W [K,N] fp32 -> Wp [K/2,N] u32 (fp16 k-pairs)
__global__ __launch_bounds__(256) void pack_w(
    const float* __restrict__ W, uint32_t* __restrict__ Wp, int K, int N)
{
    const size_t idx = (size_t)blockIdx.x * 256 + threadIdx.x;
    const int kp = (int)(idx / N), n = (int)(idx % N);
    const float lo = W[(size_t)(2 * kp) * N + n];
    const float hi = W[(size_t)(2 * kp + 1) * N + n];
    Wp[idx] = pack_f16(lo, hi);
}

// ---------------------------------------------------------------------------
// V [S,1024] bf16 -> Vt [1024,S] bf16 (transpose)
// ---------------------------------------------------------------------------
__global__ __launch_bounds__(256) void vtrans_b(
    const __nv_bfloat16* __restrict__ V, __nv_bfloat16* __restrict__ Vt)
{
    __shared__ float t[64][33];
    const int k0 = blockIdx.x * 64;
    const int d0 = blockIdx.y * 32;
    const int x = threadIdx.x & 31;
    const int y = threadIdx.x >> 5;
#pragma unroll
    for (int i = 0; i < 64; i += 8)
        t[y + i][x] = __bfloat162float(V[(size_t)(k0 + y + i) * D_MODEL + d0 + x]);
    __syncthreads();
    uint32_t* Vt32 = (uint32_t*)Vt;
#pragma unroll
    for (int p = 0; p < 4; p++) {
        const int d = y + 8 * p;
        const int j = x;
        uint32_t v = pack_bf16(t[2 * j][d], t[2 * j + 1][d]);
        Vt32[(size_t)(d0 + d) * (S_LEN / 2) + (k0 >> 1) + j] = v;
    }
}

// ---------------------------------------------------------------------------
// LayerNorm. OUT: 0=fp32, 1=bf16 pairs, 2=fp16 pairs.
// ---------------------------------------------------------------------------
template<int OUT>
__global__ __launch_bounds__(256) void ln_kernel(
    const float* __restrict__ x, const float* __restrict__ alpha,
    const float* __restrict__ beta, void* __restrict__ yv)
{
    const int row = blockIdx.x;
    const float4* xr = (const float4*)(x + (size_t)row * D_MODEL);
    const int tid = threadIdx.x;

    float4 xl = xr[tid];
    float s = xl.x + xl.y + xl.z + xl.w;

    __shared__ float sh[8];
#pragma unroll
    for (int o = 16; o > 0; o >>= 1) s += __shfl_xor_sync(0xffffffffu, s, o);
    if ((tid & 31) == 0) sh[tid >> 5] = s;
    __syncthreads();
    float mu = 0.f;
#pragma unroll
    for (int i = 0; i < 8; i++) mu += sh[i];
    mu *= (1.0f / D_MODEL);
    __syncthreads();

    float dx = xl.x - mu, dy = xl.y - mu, dz = xl.z - mu, dw = xl.w - mu;
    float v = dx * dx + dy * dy + dz * dz + dw * dw;
#pragma unroll
    for (int o = 16; o > 0; o >>= 1) v += __shfl_xor_sync(0xffffffffu, v, o);
    if ((tid & 31) == 0) sh[tid >> 5] = v;
    __syncthreads();
    float var = 0.f;
#pragma unroll
    for (int i = 0; i < 8; i++) var += sh[i];
    var *= (1.0f / (D_MODEL - 1));

    const float a = alpha[0], b = beta[0];
    const float inv = a / (sqrtf(var) + 1e-6f);
    float ox = dx * inv + b, oy = dy * inv + b;
    float oz = dz * inv + b, ow = dw * inv + b;
    if (OUT == 1) {
        uint32_t* yr = (uint32_t*)yv + (size_t)row * (D_MODEL / 2);
        yr[2 * tid + 0] = pack_bf16(ox, oy);
        yr[2 * tid + 1] = pack_bf16(oz, ow);
    } else if (OUT == 2) {
        uint32_t* yr = (uint32_t*)yv + (size_t)row * (D_MODEL / 2);
        yr[2 * tid + 0] = pack_f16(ox, oy);
        yr[2 * tid + 1] = pack_f16(oz, ow);
    } else {
        float4* yr = (float4*)yv + (size_t)row * (D_MODEL / 4);
        yr[tid] = make_float4(ox, oy, oz, ow);
    }
}

// ---------------------------------------------------------------------------
// 16-bit GEMM core (shared by bf16 QKV and fp16 generic):
// BM=128 BN=128 BK=32 (16 u32 kpairs), 256 threads, 8 warps (64x32 tiles),
// 3-stage cp.async, 1 barrier/k-tile, 2 CTAs/SM. A-frags ldmatrix.x4.
// ---------------------------------------------------------------------------
#define QASTR 36
#define QBSTR 136
#define QA_TILE (128 * QASTR)
#define QB_TILE (16 * QBSTR)
#define QSTG_U  (QA_TILE + QB_TILE)
#define G16_SMEM (3 * QSTG_U * 4)

// ---- bf16 QKV GEMM (R12, proven) ----
__global__ __launch_bounds__(256, 2) void mm_qkv_bf16(
    const uint32_t* __restrict__ A, const uint32_t* __restrict__ W3b,
    const float* __restrict__ bias,
    __nv_bfloat16* __restrict__ Q, __nv_bfloat16* __restrict__ Kout,
    __nv_bfloat16* __restrict__ V)
{
    extern __shared__ uint32_t smq[];

    const int tid  = threadIdx.x;
    const int warp = tid >> 5, lane = tid & 31;
    const int r = lane >> 2, c = lane & 3;
    const int wm = (warp >> 2) * 64, wn = (warp & 3) * 32;
    const int m0 = blockIdx.y * 128, n0 = blockIdx.x * 128;
    const int KU = D_MODEL / 2;

    const uint32_t s0 = smem_u32(smq);
    const int g2 = lane >> 3, rowin = lane & 7;
    const uint32_t aLane = (uint32_t)(((g2 & 1) * 8 + rowin) * QASTR + (g2 >> 1) * 4) * 4u;

    float acc[4][4][4];
#pragma unroll
    for (int i = 0; i < 4; i++)
#pragma unroll
        for (int j = 0; j < 4; j++)
#pragma unroll
            for (int k = 0; k < 4; k++) acc[i][j][k] = 0.f;

    const int NK = 32;

    auto load_tile = [&](int kt, int st) {
        const uint32_t ab = s0 + (uint32_t)(st * QSTG_U) * 4u;
        const uint32_t bb = ab + (uint32_t)QA_TILE * 4u;
#pragma unroll
        for (int i = 0; i < 2; i++) {
            const int id = tid + 256 * i;
            const int ar = id >> 2, akc = id & 3;
            CP_ASYNC16(ab + (uint32_t)(ar * QASTR + akc * 4) * 4u,
                       A + (size_t)(m0 + ar) * KU + kt * 16 + akc * 4);
            const int br = id >> 5, bnc = id & 31;
            CP_ASYNC16(bb + (uint32_t)(br * QBSTR + bnc * 4) * 4u,
                       W3b + (size_t)(kt * 16 + br) * QKV_N + n0 + bnc * 4);
        }
    };

    load_tile(0, 0);
    CP_COMMIT();
    load_tile(1, 1);
    CP_COMMIT();

    for (int kt = 0; kt < NK; kt++) {
        const int st = kt - (kt / 3) * 3;
        CP_WAIT(1);
        __syncthreads();
        if (kt + 2 < NK) {
            const int s2 = (kt + 2) - ((kt + 2) / 3) * 3;
            load_tile(kt + 2, s2);
        }
        CP_COMMIT();

        const uint32_t aWarp = s0 + (uint32_t)(st * QSTG_U + wm * QASTR) * 4u + aLane;
        const uint32_t* Bb = smq + st * QSTG_U + QA_TILE;
#pragma unroll
        for (int ks = 0; ks < 2; ks++) {
            uint32_t a[4][4], b[4][2];
#pragma unroll
            for (int fm = 0; fm < 4; fm++)
                ldsm_x4(a[fm], aWarp + (uint32_t)((fm * 16 * QASTR + ks * 8) * 4));
#pragma unroll
            for (int fn = 0; fn < 4; fn++) {
                const uint32_t* q = Bb + (ks * 8 + c) * QBSTR + wn + fn * 8 + r;
                b[fn][0] = q[0];
                b[fn][1] = q[4 * QBSTR];
            }
#pragma unroll
            for (int fm = 0; fm < 4; fm++)
#pragma unroll
                for (int fn = 0; fn < 4; fn++)
                    mma_bf16(acc[fm][fn], a[fm], b[fn][0], b[fn][1]);
        }
    }

    const int sel = n0 >> 10;
    const int nl0 = n0 & 1023;
    __nv_bfloat16* Cb = sel == 0 ? Q : (sel == 1 ? Kout : V);
#pragma unroll
    for (int fm = 0; fm < 4; fm++) {
        const int row0 = m0 + wm + fm * 16 + r;
        const int row1 = row0 + 8;
#pragma unroll
        for (int fn = 0; fn < 4; fn++) {
            const int colg = n0 + wn + fn * 8 + 2 * c;
            const int col  = nl0 + wn + fn * 8 + 2 * c;
            float2 bi = *(const float2*)&bias[colg];
            *(uint32_t*)&Cb[(size_t)row0 * 1024 + col] =
                pack_bf16(acc[fm][fn][0] + bi.x, acc[fm][fn][1] + bi.y);
            *(uint32_t*)&Cb[(size_t)row1 * 1024 + col] =
                pack_bf16(acc[fm][fn][2] + bi.x, acc[fm][fn][3] + bi.y);
        }
    }
}

// ---- fp16 generic GEMM: C = A@W + bias (+relu)(+res), out fp32 or fp16 ----
template<bool RELU, bool RES, bool OUT16>
__global__ __launch_bounds__(256, 2) void mm_f16k(
    const uint32_t* __restrict__ A,     // [M][KU] fp16 pairs
    const uint32_t* __restrict__ Wp,    // [KU][N] fp16 pairs
    const float* __restrict__ bias, const float* __restrict__ Rsd,
    float* __restrict__ Cf, uint32_t* __restrict__ Ch,
    int M, int N, int KU)
{
    extern __shared__ uint32_t smq[];

    const int tid  = threadIdx.x;
    const int warp = tid >> 5, lane = tid & 31;
    const int r = lane >> 2, c = lane & 3;
    const int wm = (warp >> 2) * 64, wn = (warp & 3) * 32;
    const int m0 = blockIdx.y * 128, n0 = blockIdx.x * 128;

    const uint32_t s0 = smem_u32(smq);
    const int g2 = lane >> 3, rowin = lane & 7;
    const uint32_t aLane = (uint32_t)(((g2 & 1) * 8 + rowin) * QASTR + (g2 >> 1) * 4) * 4u;

    float acc[4][4][4];
#pragma unroll
    for (int i = 0; i < 4; i++)
#pragma unroll
        for (int j = 0; j < 4; j++)
#pragma unroll
            for (int k = 0; k < 4; k++) acc[i][j][k] = 0.f;

    const int NK = KU >> 4;

    auto load_tile = [&](int kt, int st) {
        const uint32_t ab = s0 + (uint32_t)(st * QSTG_U) * 4u;
        const uint32_t bb = ab + (uint32_t)QA_TILE * 4u;
#pragma unroll
        for (int i = 0; i < 2; i++) {
            const int id = tid + 256 * i;
            const int ar = id >> 2, akc = id & 3;
            CP_ASYNC16(ab + (uint32_t)(ar * QASTR + akc * 4) * 4u,
                       A + (size_t)(m0 + ar) * KU + kt * 16 + akc * 4);
            const int br = id >> 5, bnc = id & 31;
            CP_ASYNC16(bb + (uint32_t)(br * QBSTR + bnc * 4) * 4u,
                       Wp + (size_t)(kt * 16 + br) * N + n0 + bnc * 4);
        }
    };

    load_tile(0, 0);
    CP_COMMIT();
    load_tile(1, 1);
    CP_COMMIT();

    for (int kt = 0; kt < NK; kt++) {
        const int st = kt - (kt / 3) * 3;
        CP_WAIT(1);
        __syncthreads();
        if (kt + 2 < NK) {
            const int s2 = (kt + 2) - ((kt + 2) / 3) * 3;
            load_tile(kt + 2, s2);
        }
        CP_COMMIT();

        const uint32_t aWarp = s0 + (uint32_t)(st * QSTG_U + wm * QASTR) * 4u + aLane;
        const uint32_t* Bb = smq + st * QSTG_U + QA_TILE;
#pragma unroll
        for (int ks = 0; ks < 2; ks++) {
            uint32_t a[4][4], b[4][2];
#pragma unroll
            for (int fm = 0; fm < 4; fm++)
                ldsm_x4(a[fm], aWarp + (uint32_t)((fm * 16 * QASTR + ks * 8) * 4));
#pragma unroll
            for (int fn = 0; fn < 4; fn++) {
                const uint32_t* q = Bb + (ks * 8 + c) * QBSTR + wn + fn * 8 + r;
                b[fn][0] = q[0];
                b[fn][1] = q[4 * QBSTR];
            }
#pragma unroll
            for (int fm = 0; fm < 4; fm++)
#pragma unroll
                for (int fn = 0; fn < 4; fn++)
                    mma_f16(acc[fm][fn], a[fm], b[fn][0], b[fn][1]);
        }
    }

#pragma unroll
    for (int fm = 0; fm < 4; fm++) {
        const int row0 = m0 + wm + fm * 16 + r;
        const int row1 = row0 + 8;
#pragma unroll
        for (int fn = 0; fn < 4; fn++) {
            const int col = n0 + wn + fn * 8 + 2 * c;
            float2 bi = *(const float2*)&bias[col];
            float v0 = acc[fm][fn][0] + bi.x;
            float v1 = acc[fm][fn][1] + bi.y;
            float v2 = acc[fm][fn][2] + bi.x;
            float v3 = acc[fm][fn][3] + bi.y;
            if (RELU) {
                v0 = fmaxf(v0, 0.f); v1 = fmaxf(v1, 0.f);
                v2 = fmaxf(v2, 0.f); v3 = fmaxf(v3, 0.f);
            }
            if (RES) {
                float2 r0 = *(const float2*)&Rsd[(size_t)row0 * N + col];
                float2 r1 = *(const float2*)&Rsd[(size_t)row1 * N + col];
                v0 += r0.x; v1 += r0.y; v2 += r1.x; v3 += r1.y;
            }
            if (OUT16) {
                const int cu = (col >> 1);                  // col even
                Ch[(size_t)row0 * (N >> 1) + cu] = pack_f16(v0, v1);
                Ch[(size_t)row1 * (N >> 1) + cu] = pack_f16(v2, v3);
            } else {
                *(float2*)&Cf[(size_t)row0 * N + col] = make_float2(v0, v1);
                *(float2*)&Cf[(size_t)row1 * N + col] = make_float2(v2, v3);
            }
        }
    }
}

// ---------------------------------------------------------------------------
// Flash attention, bf16 m16n8k16 (R9), epilogue now writes fp16 ctx pairs.
// ---------------------------------------------------------------------------
#define ASTRU 36
#define QTILE_U (128 * ASTRU)
#define KTILE_U (64 * ASTRU)
#define ATT_SMEM ((QTILE_U + 4 * KTILE_U) * 4)
#define QK_SCALE 0.1803368801111364f       // 0.125 * log2(e)

__global__ __launch_bounds__(128, 2) void attn_bf16(
    const __nv_bfloat16* __restrict__ Qm, const __nv_bfloat16* __restrict__ Km,
    const __nv_bfloat16* __restrict__ Vt, uint32_t* __restrict__ CtxH)
{
    extern __shared__ uint32_t su[];
    uint32_t* Qs = su;
    uint32_t* Ks = Qs + QTILE_U;
    uint32_t* Vs = Ks + 2 * KTILE_U;

    const int tid  = threadIdx.x;
    const int warp = tid >> 5, lane = tid & 31;
    const int r = lane >> 2, c = lane & 3;
    const int wr = warp * 32;
    const int qb = blockIdx.x, h = blockIdx.y;
    const int cb = h * DK;

    const uint32_t qdst = smem_u32(Qs);
    const uint32_t kdst = smem_u32(Ks);
    const uint32_t vdst = smem_u32(Vs);

    const int g2 = lane >> 3, rowin = lane & 7;
    const uint32_t qLane = (uint32_t)(((g2 & 1) * 8 + rowin) * ASTRU + (g2 >> 1) * 4) * 4u;
    const uint32_t kLane = (uint32_t)(rowin * ASTRU + (g2 & 1) * 4) * 4u;

#pragma unroll
    for (int i = 0; i < 8; i++) {
        int id = tid + 128 * i;
        int row = id >> 3, ch = id & 7;
        CP_ASYNC16(qdst + (uint32_t)(row * ASTRU + ch * 4) * 4u,
                   Qm + (size_t)(qb * 128 + row) * D_MODEL + cb + ch * 8);
    }
#pragma unroll
    for (int i = 0; i < 4; i++) {
        int id = tid + 128 * i;
        int row = id >> 3, ch = id & 7;
        CP_ASYNC16(kdst + (uint32_t)(row * ASTRU + ch * 4) * 4u,
                   Km + (size_t)row * D_MODEL + cb + ch * 8);
        CP_ASYNC16(vdst + (uint32_t)(row * ASTRU + ch * 4) * 4u,
                   Vt + (size_t)(cb + row) * S_LEN + ch * 8);
    }
    CP_COMMIT();
    CP_WAIT(0);
    __syncthreads();

    const uint32_t qWarp = qdst + (uint32_t)(wr * ASTRU) * 4u + qLane;

    float mrow[2][2] = {{-1e30f, -1e30f}, {-1e30f, -1e30f}};
    float lrow[2][2] = {{0.f, 0.f}, {0.f, 0.f}};
    float acc[2][8][4];
#pragma unroll
    for (int i = 0; i < 2; i++)
#pragma unroll
        for (int j = 0; j < 8; j++)
#pragma unroll
            for (int k = 0; k < 4; k++) acc[i][j][k] = 0.f;

    for (int kt = 0; kt < S_LEN / 64; kt++) {
        const int buf = kt & 1;

        if (kt > 0) {
            CP_WAIT(0);
            __syncthreads();
        }
        if (kt + 1 < S_LEN / 64) {
            const int nb = buf ^ 1;
#pragma unroll
            for (int i = 0; i < 4; i++) {
                int id = tid + 128 * i;
                int row = id >> 3, ch = id & 7;
                CP_ASYNC16(kdst + (uint32_t)(nb * KTILE_U + row * ASTRU + ch * 4) * 4u,
                           Km + (size_t)((kt + 1) * 64 + row) * D_MODEL + cb + ch * 8);
                CP_ASYNC16(vdst + (uint32_t)(nb * KTILE_U + row * ASTRU + ch * 4) * 4u,
                           Vt + (size_t)(cb + row) * S_LEN + (kt + 1) * 64 + ch * 8);
            }
            CP_COMMIT();
        }

        float s[2][8][4];
#pragma unroll
        for (int i = 0; i < 2; i++)
#pragma unroll
            for (int j = 0; j < 8; j++)
#pragma unroll
                for (int k = 0; k < 4; k++) s[i][j][k] = 0.f;

        const uint32_t kTile = kdst + (uint32_t)(buf * KTILE_U) * 4u + kLane;
#pragma unroll
        for (int ks = 0; ks < 4; ks++) {
            uint32_t qf0[4], qf1[4];
            ldsm_x4(qf0, qWarp + (uint32_t)((ks * 8) * 4));
            ldsm_x4(qf1, qWarp + (uint32_t)((16 * ASTRU + ks * 8) * 4));
#pragma unroll
            for (int fn = 0; fn < 8; fn++) {
                uint32_t b0, b1;
                ldsm_x2(b0, b1, kTile + (uint32_t)((8 * fn * ASTRU + ks * 8) * 4));
                mma_bf16(s[0][fn], qf0, b0, b1);
                mma_bf16(s[1][fn], qf1, b0, b1);
            }
        }

        uint32_t pa[2][4][4];
#pragma unroll
        for (int fm = 0; fm < 2; fm++) {
            float mx0 = -1e30f, mx1 = -1e30f;
#pragma unroll
            for (int fn = 0; fn < 8; fn++) {
                mx0 = fmaxf(mx0, fmaxf(s[fm][fn][0], s[fm][fn][1]));
                mx1 = fmaxf(mx1, fmaxf(s[fm][fn][2], s[fm][fn][3]));
            }
            mx0 = fmaxf(mx0, __shfl_xor_sync(0xffffffffu, mx0, 1));
            mx0 = fmaxf(mx0, __shfl_xor_sync(0xffffffffu, mx0, 2));
            mx1 = fmaxf(mx1, __shfl_xor_sync(0xffffffffu, mx1, 1));
            mx1 = fmaxf(mx1, __shfl_xor_sync(0xffffffffu, mx1, 2));

            const float mn0 = fmaxf(mrow[fm][0], mx0);
            const float mn1 = fmaxf(mrow[fm][1], mx1);
            const float emn0 = mn0 * QK_SCALE;
            const float emn1 = mn1 * QK_SCALE;
            const float sc0 = ex2(fmaf(mrow[fm][0], QK_SCALE, -emn0));
            const float sc1 = ex2(fmaf(mrow[fm][1], QK_SCALE, -emn1));
            float ls0 = 0.f, ls1 = 0.f;
#pragma unroll
            for (int fn = 0; fn < 8; fn++) {
                float e0 = ex2(fmaf(s[fm][fn][0], QK_SCALE, -emn0));
                float e1 = ex2(fmaf(s[fm][fn][1], QK_SCALE, -emn0));
                float e2 = ex2(fmaf(s[fm][fn][2], QK_SCALE, -emn1));
                float e3 = ex2(fmaf(s[fm][fn][3], QK_SCALE, -emn1));
                ls0 += e0 + e1;
                ls1 += e2 + e3;
                pa[fm][fn >> 1][(fn & 1) * 2 + 0] = pack_bf16(e0, e1);
                pa[fm][fn >> 1][(fn & 1) * 2 + 1] = pack_bf16(e2, e3);
            }
            ls0 += __shfl_xor_sync(0xffffffffu, ls0, 1);
            ls0 += __shfl_xor_sync(0xffffffffu, ls0, 2);
            ls1 += __shfl_xor_sync(0xffffffffu, ls1, 1);
            ls1 += __shfl_xor_sync(0xffffffffu, ls1, 2);

            lrow[fm][0] = lrow[fm][0] * sc0 + ls0;
            lrow[fm][1] = lrow[fm][1] * sc1 + ls1;
            mrow[fm][0] = mn0; mrow[fm][1] = mn1;

#pragma unroll
            for (int fn = 0; fn < 8; fn++) {
                acc[fm][fn][0] *= sc0; acc[fm][fn][1] *= sc0;
                acc[fm][fn][2] *= sc1; acc[fm][fn][3] *= sc1;
            }
        }

        const uint32_t vTile = vdst + (uint32_t)(buf * KTILE_U) * 4u + kLane;
#pragma unroll
        for (int ks = 0; ks < 4; ks++) {
#pragma unroll
            for (int fn = 0; fn < 8; fn++) {
                uint32_t b0, b1;
                ldsm_x2(b0, b1, vTile + (uint32_t)((8 * fn * ASTRU + ks * 8) * 4));
                mma_bf16(acc[0][fn], pa[0][ks], b0, b1);
                mma_bf16(acc[1][fn], pa[1][ks], b0, b1);
            }
        }
    }

    // epilogue: normalize + store as fp16 pairs (cols 2c,2c+1 -> one u32)
#pragma unroll
    for (int fm = 0; fm < 2; fm++) {
        const float inv0 = 1.f / lrow[fm][0];
        const float inv1 = 1.f / lrow[fm][1];
        const int row0 = qb * 128 + wr + fm * 16 + r;
        const int row1 = row0 + 8;
#pragma unroll
        for (int fn = 0; fn < 8; fn++) {
            const int cu = ((cb + fn * 8) >> 1) + c;
            CtxH[(size_t)row0 * (D_MODEL / 2) + cu] =
                pack_f16(acc[fm][fn][0] * inv0, acc[fm][fn][1] * inv0);
            CtxH[(size_t)row1 * (D_MODEL / 2) + cu] =
                pack_f16(acc[fm][fn][2] * inv1, acc[fm][fn][3] * inv1);
        }
    }
}

// ---------------------------------------------------------------------------
extern "C" void kernel_launch(void* const* d_in, const int* in_sizes, int n_in,
                              void* d_out, int out_size)
{
    const float* x    = (const float*)d_in[0];
    const float* Wq   = (const float*)d_in[1];
    const float* bq   = (const float*)d_in[2];
    const float* Wk   = (const float*)d_in[3];
    const float* bk   = (const float*)d_in[4];
    const float* Wv   = (const float*)d_in[5];
    const float* bv   = (const float*)d_in[6];
    const float* Wo   = (const float*)d_in[7];
    const float* bo   = (const float*)d_in[8];
    const float* ln1a = (const float*)d_in[9];
    const float* ln1b = (const float*)d_in[10];
    const float* W1   = (const float*)d_in[11];
    const float* b1   = (const float*)d_in[12];
    const float* W2   = (const float*)d_in[13];
    const float* b2   = (const float*)d_in[14];
    const float* ln2a = (const float*)d_in[15];
    const float* ln2b = (const float*)d_in[16];
    float* out = (float*)d_out;

    float *x1, *b3;
    __nv_bfloat16 *h1b, *Qb, *Kb, *Vb, *Vt;
    uint32_t *W3b, *ctxh, *h2h, *f1h, *WoP, *W1P, *W2P;
    cudaGetSymbolAddress((void**)&h1b,  g_h1b);
    cudaGetSymbolAddress((void**)&Qb,   g_Qb);
    cudaGetSymbolAddress((void**)&Kb,   g_Kb);
    cudaGetSymbolAddress((void**)&Vb,   g_Vb);
    cudaGetSymbolAddress((void**)&Vt,   g_Vt);
    cudaGetSymbolAddress((void**)&ctxh, g_ctxh);
    cudaGetSymbolAddress((void**)&x1,   g_x1);
    cudaGetSymbolAddress((void**)&h2h,  g_h2h);
    cudaGetSymbolAddress((void**)&f1h,  g_f1h);
    cudaGetSymbolAddress((void**)&W3b,  g_W3b);
    cudaGetSymbolAddress((void**)&b3,   g_b3);
    cudaGetSymbolAddress((void**)&WoP,  g_WoP);
    cudaGetSymbolAddress((void**)&W1P,  g_W1P);
    cudaGetSymbolAddress((void**)&W2P,  g_W2P);

    cudaFuncSetAttribute(mm_qkv_bf16,
                         cudaFuncAttributeMaxDynamicSharedMemorySize, G16_SMEM);
    cudaFuncSetAttribute(mm_f16k<false, true, false>,
                         cudaFuncAttributeMaxDynamicSharedMemorySize, G16_SMEM);
    cudaFuncSetAttribute(mm_f16k<true, false, true>,
                         cudaFuncAttributeMaxDynamicSharedMemorySize, G16_SMEM);
    cudaFuncSetAttribute(attn_bf16,
                         cudaFuncAttributeMaxDynamicSharedMemorySize, ATT_SMEM);

    // one-time packs
    concat3b<<<(D_MODEL / 2) * QKV_N / 256, 256>>>(Wq, Wk, Wv, bq, bk, bv, W3b, b3);
    pack_w<<<(D_MODEL / 2) * D_MODEL / 256, 256>>>(Wo, WoP, D_MODEL, D_MODEL);
    pack_w<<<(D_MODEL / 2) * D_FF   / 256, 256>>>(W1, W1P, D_MODEL, D_FF);
    pack_w<<<(D_FF   / 2) * D_MODEL / 256, 256>>>(W2, W2P, D_FF, D_MODEL);

    const dim3 gQKV (QKV_N  / 128, S_LEN / 128);     // (24, 32)
    const dim3 gSmall(D_MODEL / 128, S_LEN / 128);   // (8, 32)
    const dim3 gFF1 (D_FF   / 128, S_LEN / 128);     // (32, 32)

    // residual 1
    ln_kernel<1><<<S_LEN, 256>>>(x, ln1a, ln1b, h1b);
    mm_qkv_bf16<<<gQKV, 256, G16_SMEM>>>((const uint32_t*)h1b, W3b, b3, Qb, Kb, Vb);
    vtrans_b<<<dim3(S_LEN / 64, D_MODEL / 32), 256>>>(Vb, Vt);
    attn_bf16<<<dim3(S_LEN / 128, NUM_HEADS), 128, ATT_SMEM>>>(Qb, Kb, Vt, ctxh);
    mm_f16k<false, true, false><<<gSmall, 256, G16_SMEM>>>(
        ctxh, WoP, bo, x, x1, nullptr, S_LEN, D_MODEL, D_MODEL / 2);

    // residual 2
    ln_kernel<2><<<S_LEN, 256>>>(x1, ln2a, ln2b, h2h);
    mm_f16k<true, false, true><<<gFF1, 256, G16_SMEM>>>(
        h2h, W1P, b1, nullptr, nullptr, f1h, S_LEN, D_FF, D_MODEL / 2);
    mm_f16k<false, true, false><<<gSmall, 256, G16_SMEM>>>(
        f1h, W2P, b2, x1, out, nullptr, S_LEN, D_MODEL, D_FF / 2);
}

// round 14
// speedup vs baseline: 1.6376x; 1.0865x over previous
#include <cuda_runtime.h>
#include <cuda_bf16.h>
#include <cuda_fp16.h>
#include <math.h>
#include <stdint.h>

// ---------------------------------------------------------------------------
// Encoder layer: B=1, S=4096, D=1024, H=16, dk=64, F=4096, fp32 in/out.
// R14 = R13 + BK=64 for all 16-bit GEMMs (half the barriers, 2x work/stage,
// still 2 CTAs/SM) + vectorized weight packs. Attention unchanged.
// ---------------------------------------------------------------------------

#define S_LEN 4096
#define D_MODEL 1024
#define D_FF 4096
#define NUM_HEADS 16
#define DK 64
#define QKV_N 3072

__device__ __nv_bfloat16 g_h1b[S_LEN * D_MODEL];
__device__ __nv_bfloat16 g_Qb[S_LEN * D_MODEL];
__device__ __nv_bfloat16 g_Kb[S_LEN * D_MODEL];
__device__ __nv_bfloat16 g_Vb[S_LEN * D_MODEL];
__device__ __nv_bfloat16 g_Vt[D_MODEL * S_LEN];    // [dim][key]
__device__ uint32_t g_ctxh[S_LEN * (D_MODEL / 2)]; // ctx fp16 pairs
__device__ float g_x1[S_LEN * D_MODEL];
__device__ uint32_t g_h2h[S_LEN * (D_MODEL / 2)];  // LN2 out fp16 pairs
__device__ uint32_t g_f1h[S_LEN * (D_FF / 2)];     // FFN1 out fp16 pairs
__device__ uint32_t g_W3b[(D_MODEL / 2) * QKV_N];  // bf16 k-pair packed
__device__ float g_b3[QKV_N];
__device__ uint32_t g_WoP[(D_MODEL / 2) * D_MODEL];
__device__ uint32_t g_W1P[(D_MODEL / 2) * D_FF];
__device__ uint32_t g_W2P[(D_FF / 2) * D_MODEL];

// ---------------------------------------------------------------------------
__device__ __forceinline__ void mma_bf16(float (&d)[4],
    const uint32_t (&a)[4], uint32_t b0, uint32_t b1)
{
    asm volatile(
        "mma.sync.aligned.m16n8k16.row.col.f32.bf16.bf16.f32 "
        "{%0,%1,%2,%3}, {%4,%5,%6,%7}, {%8,%9}, {%0,%1,%2,%3};\n"
        : "+f"(d[0]), "+f"(d[1]), "+f"(d[2]), "+f"(d[3])
        : "r"(a[0]), "r"(a[1]), "r"(a[2]), "r"(a[3]), "r"(b0), "r"(b1));
}
__device__ __forceinline__ void mma_f16(float (&d)[4],
    const uint32_t (&a)[4], uint32_t b0, uint32_t b1)
{
    asm volatile(
        "mma.sync.aligned.m16n8k16.row.col.f32.f16.f16.f32 "
        "{%0,%1,%2,%3}, {%4,%5,%6,%7}, {%8,%9}, {%0,%1,%2,%3};\n"
        : "+f"(d[0]), "+f"(d[1]), "+f"(d[2]), "+f"(d[3])
        : "r"(a[0]), "r"(a[1]), "r"(a[2]), "r"(a[3]), "r"(b0), "r"(b1));
}
__device__ __forceinline__ void ldsm_x4(uint32_t (&d)[4], uint32_t saddr) {
    asm volatile("ldmatrix.sync.aligned.m8n8.x4.shared.b16 {%0,%1,%2,%3}, [%4];"
        : "=r"(d[0]), "=r"(d[1]), "=r"(d[2]), "=r"(d[3]) : "r"(saddr));
}
__device__ __forceinline__ void ldsm_x2(uint32_t& d0, uint32_t& d1, uint32_t saddr) {
    asm volatile("ldmatrix.sync.aligned.m8n8.x2.shared.b16 {%0,%1}, [%2];"
        : "=r"(d0), "=r"(d1) : "r"(saddr));
}
__device__ __forceinline__ uint32_t smem_u32(const void* p) {
    return (uint32_t)__cvta_generic_to_shared(p);
}
__device__ __forceinline__ uint32_t pack_bf16(float lo, float hi) {
    __nv_bfloat162 v = __floats2bfloat162_rn(lo, hi);
    return *(uint32_t*)&v;
}
__device__ __forceinline__ uint32_t pack_f16(float lo, float hi) {
    __half2 v = __floats2half2_rn(lo, hi);
    return *(uint32_t*)&v;
}
#define CP_ASYNC16(dst, src) \
    asm volatile("cp.async.cg.shared.global [%0], [%1], 16;\n" :: "r"(dst), "l"(src))
#define CP_COMMIT() asm volatile("cp.async.commit_group;\n")
#define CP_WAIT(n)  asm volatile("cp.async.wait_group %0;\n" :: "n"(n))

__device__ __forceinline__ float ex2(float x) {
    float y;
    asm("ex2.approx.f32 %0, %1;" : "=f"(y) : "f"(x));
    return y;
}

// ---------------------------------------------------------------------------
// Concat + pack Wq|Wk|Wv -> W3b (bf16 k-pairs, vectorized x4), b3
// ---------------------------------------------------------------------------
__global__ __launch_bounds__(256) void concat3b(
    const float* __restrict__ Wq, const float* __restrict__ Wk,
    const float* __restrict__ Wv, const float* __restrict__ bq,
    const float* __restrict__ bk, const float* __restrict__ bv,
    uint32_t* __restrict__ W3b, float* __restrict__ b3)
{
    const int t = blockIdx.x * 256 + threadIdx.x;   // (512*3072)/4 threads
    const int idx = t * 4;
    const int kp = idx / QKV_N, n = idx % QKV_N;    // n multiple of 4
    const int sel = n >> 10, col = n & 1023;        // 1024 % 4 == 0: same sel
    const float* W = sel == 0 ? Wq : (sel == 1 ? Wk : Wv);
    float4 lo = *(const float4*)&W[(size_t)(2 * kp) * D_MODEL + col];
    float4 hi = *(const float4*)&W[(size_t)(2 * kp + 1) * D_MODEL + col];
    uint4 o;
    o.x = pack_bf16(lo.x, hi.x);
    o.y = pack_bf16(lo.y, hi.y);
    o.z = pack_bf16(lo.z, hi.z);
    o.w = pack_bf16(lo.w, hi.w);
    *(uint4*)&W3b[(size_t)kp * QKV_N + n] = o;
    if (idx < QKV_N) {
#pragma unroll
        for (int j = 0; j < 4; j++) {
            const int nn = n + j, ss = nn >> 10, cc = nn & 1023;
            const float* b = ss == 0 ? bq : (ss == 1 ? bk : bv);
            b3[nn] = b[cc];
        }
    }
}

// Pack W [K,N] fp32 -> Wp [K/2,N] u32 (fp16 k-pairs), vectorized x4
__global__ __launch_bounds__(256) void pack_w(
    const float* __restrict__ W, uint32_t* __restrict__ Wp, int K, int N)
{
    const size_t idx = ((size_t)blockIdx.x * 256 + threadIdx.x) * 4;
    const int kp = (int)(idx / N), n = (int)(idx % N);
    float4 lo = *(const float4*)&W[(size_t)(2 * kp) * N + n];
    float4 hi = *(const float4*)&W[(size_t)(2 * kp + 1) * N + n];
    uint4 o;
    o.x = pack_f16(lo.x, hi.x);
    o.y = pack_f16(lo.y, hi.y);
    o.z = pack_f16(lo.z, hi.z);
    o.w = pack_f16(lo.w, hi.w);
    *(uint4*)&Wp[idx] = o;
}

// ---------------------------------------------------------------------------
// V [S,1024] bf16 -> Vt [1024,S] bf16 (transpose)
// ---------------------------------------------------------------------------
__global__ __launch_bounds__(256) void vtrans_b(
    const __nv_bfloat16* __restrict__ V, __nv_bfloat16* __restrict__ Vt)
{
    __shared__ float t[64][33];
    const int k0 = blockIdx.x * 64;
    const int d0 = blockIdx.y * 32;
    const int x = threadIdx.x & 31;
    const int y = threadIdx.x >> 5;
#pragma unroll
    for (int i = 0; i < 64; i += 8)
        t[y + i][x] = __bfloat162float(V[(size_t)(k0 + y + i) * D_MODEL + d0 + x]);
    __syncthreads();
    uint32_t* Vt32 = (uint32_t*)Vt;
#pragma unroll
    for (int p = 0; p < 4; p++) {
        const int d = y + 8 * p;
        const int j = x;
        uint32_t v = pack_bf16(t[2 * j][d], t[2 * j + 1][d]);
        Vt32[(size_t)(d0 + d) * (S_LEN / 2) + (k0 >> 1) + j] = v;
    }
}

// ---------------------------------------------------------------------------
// LayerNorm. OUT: 0=fp32, 1=bf16 pairs, 2=fp16 pairs.
// ---------------------------------------------------------------------------
template<int OUT>
__global__ __launch_bounds__(256) void ln_kernel(
    const float* __restrict__ x, const float* __restrict__ alpha,
    const float* __restrict__ beta, void* __restrict__ yv)
{
    const int row = blockIdx.x;
    const float4* xr = (const float4*)(x + (size_t)row * D_MODEL);
    const int tid = threadIdx.x;

    float4 xl = xr[tid];
    float s = xl.x + xl.y + xl.z + xl.w;

    __shared__ float sh[8];
#pragma unroll
    for (int o = 16; o > 0; o >>= 1) s += __shfl_xor_sync(0xffffffffu, s, o);
    if ((tid & 31) == 0) sh[tid >> 5] = s;
    __syncthreads();
    float mu = 0.f;
#pragma unroll
    for (int i = 0; i < 8; i++) mu += sh[i];
    mu *= (1.0f / D_MODEL);
    __syncthreads();

    float dx = xl.x - mu, dy = xl.y - mu, dz = xl.z - mu, dw = xl.w - mu;
    float v = dx * dx + dy * dy + dz * dz + dw * dw;
#pragma unroll
    for (int o = 16; o > 0; o >>= 1) v += __shfl_xor_sync(0xffffffffu, v, o);
    if ((tid & 31) == 0) sh[tid >> 5] = v;
    __syncthreads();
    float var = 0.f;
#pragma unroll
    for (int i = 0; i < 8; i++) var += sh[i];
    var *= (1.0f / (D_MODEL - 1));

    const float a = alpha[0], b = beta[0];
    const float inv = a / (sqrtf(var) + 1e-6f);
    float ox = dx * inv + b, oy = dy * inv + b;
    float oz = dz * inv + b, ow = dw * inv + b;
    if (OUT == 1) {
        uint32_t* yr = (uint32_t*)yv + (size_t)row * (D_MODEL / 2);
        yr[2 * tid + 0] = pack_bf16(ox, oy);
        yr[2 * tid + 1] = pack_bf16(oz, ow);
    } else if (OUT == 2) {
        uint32_t* yr = (uint32_t*)yv + (size_t)row * (D_MODEL / 2);
        yr[2 * tid + 0] = pack_f16(ox, oy);
        yr[2 * tid + 1] = pack_f16(oz, ow);
    } else {
        float4* yr = (float4*)yv + (size_t)row * (D_MODEL / 4);
        yr[tid] = make_float4(ox, oy, oz, ow);
    }
}

// ---------------------------------------------------------------------------
// 16-bit GEMM core: BM=128 BN=128 BK=64 (32 u32 kpair rows), 256 threads,
// 8 warps (64x32 tiles), 3-stage cp.async, 1 barrier per 64-K tile, 2 CTAs/SM.
// ---------------------------------------------------------------------------
#define QASTR 36                      // u32 row stride for A (32 data + 4 pad)
#define QBSTR 136                     // u32 row stride for B (128 data + 8)
#define QA_TILE (128 * QASTR)         // 4608 u32
#define QB_TILE (32 * QBSTR)          // 4352 u32
#define QSTG_U  (QA_TILE + QB_TILE)   // 8960 u32 = 35840 B
#define G16_SMEM (3 * QSTG_U * 4)     // 107520 B

// ---- bf16 QKV GEMM ----
__global__ __launch_bounds__(256, 2) void mm_qkv_bf16(
    const uint32_t* __restrict__ A, const uint32_t* __restrict__ W3b,
    const float* __restrict__ bias,
    __nv_bfloat16* __restrict__ Q, __nv_bfloat16* __restrict__ Kout,
    __nv_bfloat16* __restrict__ V)
{
    extern __shared__ uint32_t smq[];

    const int tid  = threadIdx.x;
    const int warp = tid >> 5, lane = tid & 31;
    const int r = lane >> 2, c = lane & 3;
    const int wm = (warp >> 2) * 64, wn = (warp & 3) * 32;
    const int m0 = blockIdx.y * 128, n0 = blockIdx.x * 128;
    const int KU = D_MODEL / 2;       // 512

    const uint32_t s0 = smem_u32(smq);
    const int g2 = lane >> 3, rowin = lane & 7;
    const uint32_t aLane = (uint32_t)(((g2 & 1) * 8 + rowin) * QASTR + (g2 >> 1) * 4) * 4u;

    float acc[4][4][4];
#pragma unroll
    for (int i = 0; i < 4; i++)
#pragma unroll
        for (int j = 0; j < 4; j++)
#pragma unroll
            for (int k = 0; k < 4; k++) acc[i][j][k] = 0.f;

    const int NK = KU >> 5;           // 16

    auto load_tile = [&](int kt, int st) {
        const uint32_t ab = s0 + (uint32_t)(st * QSTG_U) * 4u;
        const uint32_t bb = ab + (uint32_t)QA_TILE * 4u;
#pragma unroll
        for (int i = 0; i < 4; i++) {
            const int id = tid + 256 * i;
            const int ar = id >> 3, akc = id & 7;
            CP_ASYNC16(ab + (uint32_t)(ar * QASTR + akc * 4) * 4u,
                       A + (size_t)(m0 + ar) * KU + kt * 32 + akc * 4);
            const int br = id >> 5, bnc = id & 31;
            CP_ASYNC16(bb + (uint32_t)(br * QBSTR + bnc * 4) * 4u,
                       W3b + (size_t)(kt * 32 + br) * QKV_N + n0 + bnc * 4);
        }
    };

    load_tile(0, 0);
    CP_COMMIT();
    load_tile(1, 1);
    CP_COMMIT();

    for (int kt = 0; kt < NK; kt++) {
        const int st = kt - (kt / 3) * 3;
        CP_WAIT(1);
        __syncthreads();
        if (kt + 2 < NK) {
            const int s2 = (kt + 2) - ((kt + 2) / 3) * 3;
            load_tile(kt + 2, s2);
        }
        CP_COMMIT();

        const uint32_t aWarp = s0 + (uint32_t)(st * QSTG_U + wm * QASTR) * 4u + aLane;
        const uint32_t* Bb = smq + st * QSTG_U + QA_TILE;
#pragma unroll
        for (int ks = 0; ks < 4; ks++) {
            uint32_t a[4][4], b[4][2];
#pragma unroll
            for (int fm = 0; fm < 4; fm++)
                ldsm_x4(a[fm], aWarp + (uint32_t)((fm * 16 * QASTR + ks * 8) * 4));
#pragma unroll
            for (int fn = 0; fn < 4; fn++) {
                const uint32_t* q = Bb + (ks * 8 + c) * QBSTR + wn + fn * 8 + r;
                b[fn][0] = q[0];
                b[fn][1] = q[4 * QBSTR];
            }
#pragma unroll
            for (int fm = 0; fm < 4; fm++)
#pragma unroll
                for (int fn = 0; fn < 4; fn++)
                    mma_bf16(acc[fm][fn], a[fm], b[fn][0], b[fn][1]);
        }
    }

    const int sel = n0 >> 10;
    const int nl0 = n0 & 1023;
    __nv_bfloat16* Cb = sel == 0 ? Q : (sel == 1 ? Kout : V);
#pragma unroll
    for (int fm = 0; fm < 4; fm++) {
        const int row0 = m0 + wm + fm * 16 + r;
        const int row1 = row0 + 8;
#pragma unroll
        for (int fn = 0; fn < 4; fn++) {
            const int colg = n0 + wn + fn * 8 + 2 * c;
            const int col  = nl0 + wn + fn * 8 + 2 * c;
            float2 bi = *(const float2*)&bias[colg];
            *(uint32_t*)&Cb[(size_t)row0 * 1024 + col] =
                pack_bf16(acc[fm][fn][0] + bi.x, acc[fm][fn][1] + bi.y);
            *(uint32_t*)&Cb[(size_t)row1 * 1024 + col] =
                pack_bf16(acc[fm][fn][2] + bi.x, acc[fm][fn][3] + bi.y);
        }
    }
}

// ---- fp16 generic GEMM: C = A@W + bias (+relu)(+res), out fp32 or fp16 ----
template<bool RELU, bool RES, bool OUT16>
__global__ __launch_bounds__(256, 2) void mm_f16k(
    const uint32_t* __restrict__ A,     // [M][KU] fp16 pairs
    const uint32_t* __restrict__ Wp,    // [KU][N] fp16 pairs
    const float* __restrict__ bias, const float* __restrict__ Rsd,
    float* __restrict__ Cf, uint32_t* __restrict__ Ch,
    int M, int N, int KU)
{
    extern __shared__ uint32_t smq[];

    const int tid  = threadIdx.x;
    const int warp = tid >> 5, lane = tid & 31;
    const int r = lane >> 2, c = lane & 3;
    const int wm = (warp >> 2) * 64, wn = (warp & 3) * 32;
    const int m0 = blockIdx.y * 128, n0 = blockIdx.x * 128;

    const uint32_t s0 = smem_u32(smq);
    const int g2 = lane >> 3, rowin = lane & 7;
    const uint32_t aLane = (uint32_t)(((g2 & 1) * 8 + rowin) * QASTR + (g2 >> 1) * 4) * 4u;

    float acc[4][4][4];
#pragma unroll
    for (int i = 0; i < 4; i++)
#pragma unroll
        for (int j = 0; j < 4; j++)
#pragma unroll
            for (int k = 0; k < 4; k++) acc[i][j][k] = 0.f;

    const int NK = KU >> 5;

    auto load_tile = [&](int kt, int st) {
        const uint32_t ab = s0 + (uint32_t)(st * QSTG_U) * 4u;
        const uint32_t bb = ab + (uint32_t)QA_TILE * 4u;
#pragma unroll
        for (int i = 0; i < 4; i++) {
            const int id = tid + 256 * i;
            const int ar = id >> 3, akc = id & 7;
            CP_ASYNC16(ab + (uint32_t)(ar * QASTR + akc * 4) * 4u,
                       A + (size_t)(m0 + ar) * KU + kt * 32 + akc * 4);
            const int br = id >> 5, bnc = id & 31;
            CP_ASYNC16(bb + (uint32_t)(br * QBSTR + bnc * 4) * 4u,
                       Wp + (size_t)(kt * 32 + br) * N + n0 + bnc * 4);
        }
    };

    load_tile(0, 0);
    CP_COMMIT();
    load_tile(1, 1);
    CP_COMMIT();

    for (int kt = 0; kt < NK; kt++) {
        const int st = kt - (kt / 3) * 3;
        CP_WAIT(1);
        __syncthreads();
        if (kt + 2 < NK) {
            const int s2 = (kt + 2) - ((kt + 2) / 3) * 3;
            load_tile(kt + 2, s2);
        }
        CP_COMMIT();

        const uint32_t aWarp = s0 + (uint32_t)(st * QSTG_U + wm * QASTR) * 4u + aLane;
        const uint32_t* Bb = smq + st * QSTG_U + QA_TILE;
#pragma unroll
        for (int ks = 0; ks < 4; ks++) {
            uint32_t a[4][4], b[4][2];
#pragma unroll
            for (int fm = 0; fm < 4; fm++)
                ldsm_x4(a[fm], aWarp + (uint32_t)((fm * 16 * QASTR + ks * 8) * 4));
#pragma unroll
            for (int fn = 0; fn < 4; fn++) {
                const uint32_t* q = Bb + (ks * 8 + c) * QBSTR + wn + fn * 8 + r;
                b[fn][0] = q[0];
                b[fn][1] = q[4 * QBSTR];
            }
#pragma unroll
            for (int fm = 0; fm < 4; fm++)
#pragma unroll
                for (int fn = 0; fn < 4; fn++)
                    mma_f16(acc[fm][fn], a[fm], b[fn][0], b[fn][1]);
        }
    }

#pragma unroll
    for (int fm = 0; fm < 4; fm++) {
        const int row0 = m0 + wm + fm * 16 + r;
        const int row1 = row0 + 8;
#pragma unroll
        for (int fn = 0; fn < 4; fn++) {
            const int col = n0 + wn + fn * 8 + 2 * c;
            float2 bi = *(const float2*)&bias[col];
            float v0 = acc[fm][fn][0] + bi.x;
            float v1 = acc[fm][fn][1] + bi.y;
            float v2 = acc[fm][fn][2] + bi.x;
            float v3 = acc[fm][fn][3] + bi.y;
            if (RELU) {
                v0 = fmaxf(v0, 0.f); v1 = fmaxf(v1, 0.f);
                v2 = fmaxf(v2, 0.f); v3 = fmaxf(v3, 0.f);
            }
            if (RES) {
                float2 r0 = *(const float2*)&Rsd[(size_t)row0 * N + col];
                float2 r1 = *(const float2*)&Rsd[(size_t)row1 * N + col];
                v0 += r0.x; v1 += r0.y; v2 += r1.x; v3 += r1.y;
            }
            if (OUT16) {
                const int cu = (col >> 1);
                Ch[(size_t)row0 * (N >> 1) + cu] = pack_f16(v0, v1);
                Ch[(size_t)row1 * (N >> 1) + cu] = pack_f16(v2, v3);
            } else {
                *(float2*)&Cf[(size_t)row0 * N + col] = make_float2(v0, v1);
                *(float2*)&Cf[(size_t)row1 * N + col] = make_float2(v2, v3);
            }
        }
    }
}

// ---------------------------------------------------------------------------
// Flash attention, bf16 m16n8k16 (R13, unchanged; fp16 ctx out).
// ---------------------------------------------------------------------------
#define ASTRU 36
#define QTILE_U (128 * ASTRU)
#define KTILE_U (64 * ASTRU)
#define ATT_SMEM ((QTILE_U + 4 * KTILE_U) * 4)
#define QK_SCALE 0.1803368801111364f       // 0.125 * log2(e)

__global__ __launch_bounds__(128, 2) void attn_bf16(
    const __nv_bfloat16* __restrict__ Qm, const __nv_bfloat16* __restrict__ Km,
    const __nv_bfloat16* __restrict__ Vt, uint32_t* __restrict__ CtxH)
{
    extern __shared__ uint32_t su[];
    uint32_t* Qs = su;
    uint32_t* Ks = Qs + QTILE_U;
    uint32_t* Vs = Ks + 2 * KTILE_U;

    const int tid  = threadIdx.x;
    const int warp = tid >> 5, lane = tid & 31;
    const int r = lane >> 2, c = lane & 3;
    const int wr = warp * 32;
    const int qb = blockIdx.x, h = blockIdx.y;
    const int cb = h * DK;

    const uint32_t qdst = smem_u32(Qs);
    const uint32_t kdst = smem_u32(Ks);
    const uint32_t vdst = smem_u32(Vs);

    const int g2 = lane >> 3, rowin = lane & 7;
    const uint32_t qLane = (uint32_t)(((g2 & 1) * 8 + rowin) * ASTRU + (g2 >> 1) * 4) * 4u;
    const uint32_t kLane = (uint32_t)(rowin * ASTRU + (g2 & 1) * 4) * 4u;

#pragma unroll
    for (int i = 0; i < 8; i++) {
        int id = tid + 128 * i;
        int row = id >> 3, ch = id & 7;
        CP_ASYNC16(qdst + (uint32_t)(row * ASTRU + ch * 4) * 4u,
                   Qm + (size_t)(qb * 128 + row) * D_MODEL + cb + ch * 8);
    }
#pragma unroll
    for (int i = 0; i < 4; i++) {
        int id = tid + 128 * i;
        int row = id >> 3, ch = id & 7;
        CP_ASYNC16(kdst + (uint32_t)(row * ASTRU + ch * 4) * 4u,
                   Km + (size_t)row * D_MODEL + cb + ch * 8);
        CP_ASYNC16(vdst + (uint32_t)(row * ASTRU + ch * 4) * 4u,
                   Vt + (size_t)(cb + row) * S_LEN + ch * 8);
    }
    CP_COMMIT();
    CP_WAIT(0);
    __syncthreads();

    const uint32_t qWarp = qdst + (uint32_t)(wr * ASTRU) * 4u + qLane;

    float mrow[2][2] = {{-1e30f, -1e30f}, {-1e30f, -1e30f}};
    float lrow[2][2] = {{0.f, 0.f}, {0.f, 0.f}};
    float acc[2][8][4];
#pragma unroll
    for (int i = 0; i < 2; i++)
#pragma unroll
        for (int j = 0; j < 8; j++)
#pragma unroll
            for (int k = 0; k < 4; k++) acc[i][j][k] = 0.f;

    for (int kt = 0; kt < S_LEN / 64; kt++) {
        const int buf = kt & 1;

        if (kt > 0) {
            CP_WAIT(0);
            __syncthreads();
        }
        if (kt + 1 < S_LEN / 64) {
            const int nb = buf ^ 1;
#pragma unroll
            for (int i = 0; i < 4; i++) {
                int id = tid + 128 * i;
                int row = id >> 3, ch = id & 7;
                CP_ASYNC16(kdst + (uint32_t)(nb * KTILE_U + row * ASTRU + ch * 4) * 4u,
                           Km + (size_t)((kt + 1) * 64 + row) * D_MODEL + cb + ch * 8);
                CP_ASYNC16(vdst + (uint32_t)(nb * KTILE_U + row * ASTRU + ch * 4) * 4u,
                           Vt + (size_t)(cb + row) * S_LEN + (kt + 1) * 64 + ch * 8);
            }
            CP_COMMIT();
        }

        float s[2][8][4];
#pragma unroll
        for (int i = 0; i < 2; i++)
#pragma unroll
            for (int j = 0; j < 8; j++)
#pragma unroll
                for (int k = 0; k < 4; k++) s[i][j][k] = 0.f;

        const uint32_t kTile = kdst + (uint32_t)(buf * KTILE_U) * 4u + kLane;
#pragma unroll
        for (int ks = 0; ks < 4; ks++) {
            uint32_t qf0[4], qf1[4];
            ldsm_x4(qf0, qWarp + (uint32_t)((ks * 8) * 4));
            ldsm_x4(qf1, qWarp + (uint32_t)((16 * ASTRU + ks * 8) * 4));
#pragma unroll
            for (int fn = 0; fn < 8; fn++) {
                uint32_t b0, b1;
                ldsm_x2(b0, b1, kTile + (uint32_t)((8 * fn * ASTRU + ks * 8) * 4));
                mma_bf16(s[0][fn], qf0, b0, b1);
                mma_bf16(s[1][fn], qf1, b0, b1);
            }
        }

        uint32_t pa[2][4][4];
#pragma unroll
        for (int fm = 0; fm < 2; fm++) {
            float mx0 = -1e30f, mx1 = -1e30f;
#pragma unroll
            for (int fn = 0; fn < 8; fn++) {
                mx0 = fmaxf(mx0, fmaxf(s[fm][fn][0], s[fm][fn][1]));
                mx1 = fmaxf(mx1, fmaxf(s[fm][fn][2], s[fm][fn][3]));
            }
            mx0 = fmaxf(mx0, __shfl_xor_sync(0xffffffffu, mx0, 1));
            mx0 = fmaxf(mx0, __shfl_xor_sync(0xffffffffu, mx0, 2));
            mx1 = fmaxf(mx1, __shfl_xor_sync(0xffffffffu, mx1, 1));
            mx1 = fmaxf(mx1, __shfl_xor_sync(0xffffffffu, mx1, 2));

            const float mn0 = fmaxf(mrow[fm][0], mx0);
            const float mn1 = fmaxf(mrow[fm][1], mx1);
            const float emn0 = mn0 * QK_SCALE;
            const float emn1 = mn1 * QK_SCALE;
            const float sc0 = ex2(fmaf(mrow[fm][0], QK_SCALE, -emn0));
            const float sc1 = ex2(fmaf(mrow[fm][1], QK_SCALE, -emn1));
            float ls0 = 0.f, ls1 = 0.f;
#pragma unroll
            for (int fn = 0; fn < 8; fn++) {
                float e0 = ex2(fmaf(s[fm][fn][0], QK_SCALE, -emn0));
                float e1 = ex2(fmaf(s[fm][fn][1], QK_SCALE, -emn0));
                float e2 = ex2(fmaf(s[fm][fn][2], QK_SCALE, -emn1));
                float e3 = ex2(fmaf(s[fm][fn][3], QK_SCALE, -emn1));
                ls0 += e0 + e1;
                ls1 += e2 + e3;
                pa[fm][fn >> 1][(fn & 1) * 2 + 0] = pack_bf16(e0, e1);
                pa[fm][fn >> 1][(fn & 1) * 2 + 1] = pack_bf16(e2, e3);
            }
            ls0 += __shfl_xor_sync(0xffffffffu, ls0, 1);
            ls0 += __shfl_xor_sync(0xffffffffu, ls0, 2);
            ls1 += __shfl_xor_sync(0xffffffffu, ls1, 1);
            ls1 += __shfl_xor_sync(0xffffffffu, ls1, 2);

            lrow[fm][0] = lrow[fm][0] * sc0 + ls0;
            lrow[fm][1] = lrow[fm][1] * sc1 + ls1;
            mrow[fm][0] = mn0; mrow[fm][1] = mn1;

#pragma unroll
            for (int fn = 0; fn < 8; fn++) {
                acc[fm][fn][0] *= sc0; acc[fm][fn][1] *= sc0;
                acc[fm][fn][2] *= sc1; acc[fm][fn][3] *= sc1;
            }
        }

        const uint32_t vTile = vdst + (uint32_t)(buf * KTILE_U) * 4u + kLane;
#pragma unroll
        for (int ks = 0; ks < 4; ks++) {
#pragma unroll
            for (int fn = 0; fn < 8; fn++) {
                uint32_t b0, b1;
                ldsm_x2(b0, b1, vTile + (uint32_t)((8 * fn * ASTRU + ks * 8) * 4));
                mma_bf16(acc[0][fn], pa[0][ks], b0, b1);
                mma_bf16(acc[1][fn], pa[1][ks], b0, b1);
            }
        }
    }

#pragma unroll
    for (int fm = 0; fm < 2; fm++) {
        const float inv0 = 1.f / lrow[fm][0];
        const float inv1 = 1.f / lrow[fm][1];
        const int row0 = qb * 128 + wr + fm * 16 + r;
        const int row1 = row0 + 8;
#pragma unroll
        for (int fn = 0; fn < 8; fn++) {
            const int cu = ((cb + fn * 8) >> 1) + c;
            CtxH[(size_t)row0 * (D_MODEL / 2) + cu] =
                pack_f16(acc[fm][fn][0] * inv0, acc[fm][fn][1] * inv0);
            CtxH[(size_t)row1 * (D_MODEL / 2) + cu] =
                pack_f16(acc[fm][fn][2] * inv1, acc[fm][fn][3] * inv1);
        }
    }
}

// ---------------------------------------------------------------------------
extern "C" void kernel_launch(void* const* d_in, const int* in_sizes, int n_in,
                              void* d_out, int out_size)
{
    const float* x    = (const float*)d_in[0];
    const float* Wq   = (const float*)d_in[1];
    const float* bq   = (const float*)d_in[2];
    const float* Wk   = (const float*)d_in[3];
    const float* bk   = (const float*)d_in[4];
    const float* Wv   = (const float*)d_in[5];
    const float* bv   = (const float*)d_in[6];
    const float* Wo   = (const float*)d_in[7];
    const float* bo   = (const float*)d_in[8];
    const float* ln1a = (const float*)d_in[9];
    const float* ln1b = (const float*)d_in[10];
    const float* W1   = (const float*)d_in[11];
    const float* b1   = (const float*)d_in[12];
    const float* W2   = (const float*)d_in[13];
    const float* b2   = (const float*)d_in[14];
    const float* ln2a = (const float*)d_in[15];
    const float* ln2b = (const float*)d_in[16];
    float* out = (float*)d_out;

    float *x1, *b3;
    __nv_bfloat16 *h1b, *Qb, *Kb, *Vb, *Vt;
    uint32_t *W3b, *ctxh, *h2h, *f1h, *WoP, *W1P, *W2P;
    cudaGetSymbolAddress((void**)&h1b,  g_h1b);
    cudaGetSymbolAddress((void**)&Qb,   g_Qb);
    cudaGetSymbolAddress((void**)&Kb,   g_Kb);
    cudaGetSymbolAddress((void**)&Vb,   g_Vb);
    cudaGetSymbolAddress((void**)&Vt,   g_Vt);
    cudaGetSymbolAddress((void**)&ctxh, g_ctxh);
    cudaGetSymbolAddress((void**)&x1,   g_x1);
    cudaGetSymbolAddress((void**)&h2h,  g_h2h);
    cudaGetSymbolAddress((void**)&f1h,  g_f1h);
    cudaGetSymbolAddress((void**)&W3b,  g_W3b);
    cudaGetSymbolAddress((void**)&b3,   g_b3);
    cudaGetSymbolAddress((void**)&WoP,  g_WoP);
    cudaGetSymbolAddress((void**)&W1P,  g_W1P);
    cudaGetSymbolAddress((void**)&W2P,  g_W2P);

    cudaFuncSetAttribute(mm_qkv_bf16,
                         cudaFuncAttributeMaxDynamicSharedMemorySize, G16_SMEM);
    cudaFuncSetAttribute(mm_f16k<false, true, false>,
                         cudaFuncAttributeMaxDynamicSharedMemorySize, G16_SMEM);
    cudaFuncSetAttribute(mm_f16k<true, false, true>,
                         cudaFuncAttributeMaxDynamicSharedMemorySize, G16_SMEM);
    cudaFuncSetAttribute(attn_bf16,
                         cudaFuncAttributeMaxDynamicSharedMemorySize, ATT_SMEM);

    // one-time packs (vectorized x4)
    concat3b<<<(D_MODEL / 2) * QKV_N / 1024, 256>>>(Wq, Wk, Wv, bq, bk, bv, W3b, b3);
    pack_w<<<(D_MODEL / 2) * D_MODEL / 1024, 256>>>(Wo, WoP, D_MODEL, D_MODEL);
    pack_w<<<(D_MODEL / 2) * D_FF   / 1024, 256>>>(W1, W1P, D_MODEL, D_FF);
    pack_w<<<(D_FF   / 2) * D_MODEL / 1024, 256>>>(W2, W2P, D_FF, D_MODEL);

    const dim3 gQKV (QKV_N  / 128, S_LEN / 128);     // (24, 32)
    const dim3 gSmall(D_MODEL / 128, S_LEN / 128);   // (8, 32)
    const dim3 gFF1 (D_FF   / 128, S_LEN / 128);     // (32, 32)

    // residual 1
    ln_kernel<1><<<S_LEN, 256>>>(x, ln1a, ln1b, h1b);
    mm_qkv_bf16<<<gQKV, 256, G16_SMEM>>>((const uint32_t*)h1b, W3b, b3, Qb, Kb, Vb);
    vtrans_b<<<dim3(S_LEN / 64, D_MODEL / 32), 256>>>(Vb, Vt);
    attn_bf16<<<dim3(S_LEN / 128, NUM_HEADS), 128, ATT_SMEM>>>(Qb, Kb, Vt, ctxh);
    mm_f16k<false, true, false><<<gSmall, 256, G16_SMEM>>>(
        ctxh, WoP, bo, x, x1, nullptr, S_LEN, D_MODEL, D_MODEL / 2);

    // residual 2
    ln_kernel<2><<<S_LEN, 256>>>(x1, ln2a, ln2b, h2h);
    mm_f16k<true, false, true><<<gFF1, 256, G16_SMEM>>>(
        h2h, W1P, b1, nullptr, nullptr, f1h, S_LEN, D_FF, D_MODEL / 2);
    mm_f16k<false, true, false><<<gSmall, 256, G16_SMEM>>>(
        f1h, W2P, b2, x1, out, nullptr, S_LEN, D_MODEL, D_FF / 2);
}

// round 16
// speedup vs baseline: 1.6538x; 1.0099x over previous
#include <cuda_runtime.h>
#include <cuda_bf16.h>
#include <cuda_fp16.h>
#include <math.h>
#include <stdint.h>

// ---------------------------------------------------------------------------
// Encoder layer: B=1, S=4096, D=1024, H=16, dk=64, F=4096, fp32 in/out.
// R16 = R14 + attention 128-key double-buffered tiles (two 64-key chunks per
// barrier; V tile correctly dim-major per half) + fused weight-pack kernel.
// ---------------------------------------------------------------------------

#define S_LEN 4096
#define D_MODEL 1024
#define D_FF 4096
#define NUM_HEADS 16
#define DK 64
#define QKV_N 3072

__device__ __nv_bfloat16 g_h1b[S_LEN * D_MODEL];
__device__ __nv_bfloat16 g_Qb[S_LEN * D_MODEL];
__device__ __nv_bfloat16 g_Kb[S_LEN * D_MODEL];
__device__ __nv_bfloat16 g_Vb[S_LEN * D_MODEL];
__device__ __nv_bfloat16 g_Vt[D_MODEL * S_LEN];    // [dim][key]
__device__ uint32_t g_ctxh[S_LEN * (D_MODEL / 2)]; // ctx fp16 pairs
__device__ float g_x1[S_LEN * D_MODEL];
__device__ uint32_t g_h2h[S_LEN * (D_MODEL / 2)];  // LN2 out fp16 pairs
__device__ uint32_t g_f1h[S_LEN * (D_FF / 2)];     // FFN1 out fp16 pairs
__device__ uint32_t g_W3b[(D_MODEL / 2) * QKV_N];  // bf16 k-pair packed
__device__ float g_b3[QKV_N];
__device__ uint32_t g_WoP[(D_MODEL / 2) * D_MODEL];
__device__ uint32_t g_W1P[(D_MODEL / 2) * D_FF];
__device__ uint32_t g_W2P[(D_FF / 2) * D_MODEL];

// ---------------------------------------------------------------------------
__device__ __forceinline__ void mma_bf16(float (&d)[4],
    const uint32_t (&a)[4], uint32_t b0, uint32_t b1)
{
    asm volatile(
        "mma.sync.aligned.m16n8k16.row.col.f32.bf16.bf16.f32 "
        "{%0,%1,%2,%3}, {%4,%5,%6,%7}, {%8,%9}, {%0,%1,%2,%3};\n"
        : "+f"(d[0]), "+f"(d[1]), "+f"(d[2]), "+f"(d[3])
        : "r"(a[0]), "r"(a[1]), "r"(a[2]), "r"(a[3]), "r"(b0), "r"(b1));
}
__device__ __forceinline__ void mma_f16(float (&d)[4],
    const uint32_t (&a)[4], uint32_t b0, uint32_t b1)
{
    asm volatile(
        "mma.sync.aligned.m16n8k16.row.col.f32.f16.f16.f32 "
        "{%0,%1,%2,%3}, {%4,%5,%6,%7}, {%8,%9}, {%0,%1,%2,%3};\n"
        : "+f"(d[0]), "+f"(d[1]), "+f"(d[2]), "+f"(d[3])
        : "r"(a[0]), "r"(a[1]), "r"(a[2]), "r"(a[3]), "r"(b0), "r"(b1));
}
__device__ __forceinline__ void ldsm_x4(uint32_t (&d)[4], uint32_t saddr) {
    asm volatile("ldmatrix.sync.aligned.m8n8.x4.shared.b16 {%0,%1,%2,%3}, [%4];"
        : "=r"(d[0]), "=r"(d[1]), "=r"(d[2]), "=r"(d[3]) : "r"(saddr));
}
__device__ __forceinline__ void ldsm_x2(uint32_t& d0, uint32_t& d1, uint32_t saddr) {
    asm volatile("ldmatrix.sync.aligned.m8n8.x2.shared.b16 {%0,%1}, [%2];"
        : "=r"(d0), "=r"(d1) : "r"(saddr));
}
__device__ __forceinline__ uint32_t smem_u32(const void* p) {
    return (uint32_t)__cvta_generic_to_shared(p);
}
__device__ __forceinline__ uint32_t pack_bf16(float lo, float hi) {
    __nv_bfloat162 v = __floats2bfloat162_rn(lo, hi);
    return *(uint32_t*)&v;
}
__device__ __forceinline__ uint32_t pack_f16(float lo, float hi) {
    __half2 v = __floats2half2_rn(lo, hi);
    return *(uint32_t*)&v;
}
#define CP_ASYNC16(dst, src) \
    asm volatile("cp.async.cg.shared.global [%0], [%1], 16;\n" :: "r"(dst), "l"(src))
#define CP_COMMIT() asm volatile("cp.async.commit_group;\n")
#define CP_WAIT(n)  asm volatile("cp.async.wait_group %0;\n" :: "n"(n))

__device__ __forceinline__ float ex2(float x) {
    float y;
    asm("ex2.approx.f32 %0, %1;" : "=f"(y) : "f"(x));
    return y;
}

// ---------------------------------------------------------------------------
// Concat + pack Wq|Wk|Wv -> W3b (bf16 k-pairs, vectorized x4), b3
// ---------------------------------------------------------------------------
__global__ __launch_bounds__(256) void concat3b(
    const float* __restrict__ Wq, const float* __restrict__ Wk,
    const float* __restrict__ Wv, const float* __restrict__ bq,
    const float* __restrict__ bk, const float* __restrict__ bv,
    uint32_t* __restrict__ W3b, float* __restrict__ b3)
{
    const int t = blockIdx.x * 256 + threadIdx.x;
    const int idx = t * 4;
    const int kp = idx / QKV_N, n = idx % QKV_N;
    const int sel = n >> 10, col = n & 1023;
    const float* W = sel == 0 ? Wq : (sel == 1 ? Wk : Wv);
    float4 lo = *(const float4*)&W[(size_t)(2 * kp) * D_MODEL + col];
    float4 hi = *(const float4*)&W[(size_t)(2 * kp + 1) * D_MODEL + col];
    uint4 o;
    o.x = pack_bf16(lo.x, hi.x);
    o.y = pack_bf16(lo.y, hi.y);
    o.z = pack_bf16(lo.z, hi.z);
    o.w = pack_bf16(lo.w, hi.w);
    *(uint4*)&W3b[(size_t)kp * QKV_N + n] = o;
    if (idx < QKV_N) {
#pragma unroll
        for (int j = 0; j < 4; j++) {
            const int nn = n + j, ss = nn >> 10, cc = nn & 1023;
            const float* b = ss == 0 ? bq : (ss == 1 ? bk : bv);
            b3[nn] = b[cc];
        }
    }
}

// Fused pack: Wo (1024x1024), W1 (1024x4096), W2 (4096x1024) -> fp16 k-pairs
#define PACK_Q0 (D_MODEL / 2 * D_MODEL / 4)   // 131072 quads (Wo)
#define PACK_Q1 (D_MODEL / 2 * D_FF / 4)      // 524288 quads (W1)
#define PACK_Q2 (D_FF / 2 * D_MODEL / 4)      // 524288 quads (W2)
__global__ __launch_bounds__(256) void pack_all(
    const float* __restrict__ Wo, const float* __restrict__ W1,
    const float* __restrict__ W2, uint32_t* __restrict__ WoP,
    uint32_t* __restrict__ W1P, uint32_t* __restrict__ W2P)
{
    int t = blockIdx.x * 256 + threadIdx.x;
    const float* W;
    uint32_t* Wp;
    int N;
    if (t < PACK_Q0) {
        W = Wo; Wp = WoP; N = D_MODEL;
    } else if (t < PACK_Q0 + PACK_Q1) {
        t -= PACK_Q0; W = W1; Wp = W1P; N = D_FF;
    } else {
        t -= PACK_Q0 + PACK_Q1; W = W2; Wp = W2P; N = D_MODEL;
    }
    const size_t idx = (size_t)t * 4;
    const int kp = (int)(idx / N), n = (int)(idx % N);
    float4 lo = *(const float4*)&W[(size_t)(2 * kp) * N + n];
    float4 hi = *(const float4*)&W[(size_t)(2 * kp + 1) * N + n];
    uint4 o;
    o.x = pack_f16(lo.x, hi.x);
    o.y = pack_f16(lo.y, hi.y);
    o.z = pack_f16(lo.z, hi.z);
    o.w = pack_f16(lo.w, hi.w);
    *(uint4*)&Wp[idx] = o;
}

// ---------------------------------------------------------------------------
// V [S,1024] bf16 -> Vt [1024,S] bf16 (transpose)
// ---------------------------------------------------------------------------
__global__ __launch_bounds__(256) void vtrans_b(
    const __nv_bfloat16* __restrict__ V, __nv_bfloat16* __restrict__ Vt)
{
    __shared__ float t[64][33];
    const int k0 = blockIdx.x * 64;
    const int d0 = blockIdx.y * 32;
    const int x = threadIdx.x & 31;
    const int y = threadIdx.x >> 5;
#pragma unroll
    for (int i = 0; i < 64; i += 8)
        t[y + i][x] = __bfloat162float(V[(size_t)(k0 + y + i) * D_MODEL + d0 + x]);
    __syncthreads();
    uint32_t* Vt32 = (uint32_t*)Vt;
#pragma unroll
    for (int p = 0; p < 4; p++) {
        const int d = y + 8 * p;
        const int j = x;
        uint32_t v = pack_bf16(t[2 * j][d], t[2 * j + 1][d]);
        Vt32[(size_t)(d0 + d) * (S_LEN / 2) + (k0 >> 1) + j] = v;
    }
}

// ---------------------------------------------------------------------------
// LayerNorm. OUT: 0=fp32, 1=bf16 pairs, 2=fp16 pairs.
// ---------------------------------------------------------------------------
template<int OUT>
__global__ __launch_bounds__(256) void ln_kernel(
    const float* __restrict__ x, const float* __restrict__ alpha,
    const float* __restrict__ beta, void* __restrict__ yv)
{
    const int row = blockIdx.x;
    const float4* xr = (const float4*)(x + (size_t)row * D_MODEL);
    const int tid = threadIdx.x;

    float4 xl = xr[tid];
    float s = xl.x + xl.y + xl.z + xl.w;

    __shared__ float sh[8];
#pragma unroll
    for (int o = 16; o > 0; o >>= 1) s += __shfl_xor_sync(0xffffffffu, s, o);
    if ((tid & 31) == 0) sh[tid >> 5] = s;
    __syncthreads();
    float mu = 0.f;
#pragma unroll
    for (int i = 0; i < 8; i++) mu += sh[i];
    mu *= (1.0f / D_MODEL);
    __syncthreads();

    float dx = xl.x - mu, dy = xl.y - mu, dz = xl.z - mu, dw = xl.w - mu;
    float v = dx * dx + dy * dy + dz * dz + dw * dw;
#pragma unroll
    for (int o = 16; o > 0; o >>= 1) v += __shfl_xor_sync(0xffffffffu, v, o);
    if ((tid & 31) == 0) sh[tid >> 5] = v;
    __syncthreads();
    float var = 0.f;
#pragma unroll
    for (int i = 0; i < 8; i++) var += sh[i];
    var *= (1.0f / (D_MODEL - 1));

    const float a = alpha[0], b = beta[0];
    const float inv = a / (sqrtf(var) + 1e-6f);
    float ox = dx * inv + b, oy = dy * inv + b;
    float oz = dz * inv + b, ow = dw * inv + b;
    if (OUT == 1) {
        uint32_t* yr = (uint32_t*)yv + (size_t)row * (D_MODEL / 2);
        yr[2 * tid + 0] = pack_bf16(ox, oy);
        yr[2 * tid + 1] = pack_bf16(oz, ow);
    } else if (OUT == 2) {
        uint32_t* yr = (uint32_t*)yv + (size_t)row * (D_MODEL / 2);
        yr[2 * tid + 0] = pack_f16(ox, oy);
        yr[2 * tid + 1] = pack_f16(oz, ow);
    } else {
        float4* yr = (float4*)yv + (size_t)row * (D_MODEL / 4);
        yr[tid] = make_float4(ox, oy, oz, ow);
    }
}

// ---------------------------------------------------------------------------
// 16-bit GEMM core: BM=128 BN=128 BK=64 (32 u32 kpair rows), 256 threads,
// 8 warps (64x32 tiles), 3-stage cp.async, 1 barrier per 64-K tile, 2 CTAs/SM.
// ---------------------------------------------------------------------------
#define QASTR 36
#define QBSTR 136
#define QA_TILE (128 * QASTR)
#define QB_TILE (32 * QBSTR)
#define QSTG_U  (QA_TILE + QB_TILE)
#define G16_SMEM (3 * QSTG_U * 4)

// ---- bf16 QKV GEMM ----
__global__ __launch_bounds__(256, 2) void mm_qkv_bf16(
    const uint32_t* __restrict__ A, const uint32_t* __restrict__ W3b,
    const float* __restrict__ bias,
    __nv_bfloat16* __restrict__ Q, __nv_bfloat16* __restrict__ Kout,
    __nv_bfloat16* __restrict__ V)
{
    extern __shared__ uint32_t smq[];

    const int tid  = threadIdx.x;
    const int warp = tid >> 5, lane = tid & 31;
    const int r = lane >> 2, c = lane & 3;
    const int wm = (warp >> 2) * 64, wn = (warp & 3) * 32;
    const int m0 = blockIdx.y * 128, n0 = blockIdx.x * 128;
    const int KU = D_MODEL / 2;

    const uint32_t s0 = smem_u32(smq);
    const int g2 = lane >> 3, rowin = lane & 7;
    const uint32_t aLane = (uint32_t)(((g2 & 1) * 8 + rowin) * QASTR + (g2 >> 1) * 4) * 4u;

    float acc[4][4][4];
#pragma unroll
    for (int i = 0; i < 4; i++)
#pragma unroll
        for (int j = 0; j < 4; j++)
#pragma unroll
            for (int k = 0; k < 4; k++) acc[i][j][k] = 0.f;

    const int NK = KU >> 5;

    auto load_tile = [&](int kt, int st) {
        const uint32_t ab = s0 + (uint32_t)(st * QSTG_U) * 4u;
        const uint32_t bb = ab + (uint32_t)QA_TILE * 4u;
#pragma unroll
        for (int i = 0; i < 4; i++) {
            const int id = tid + 256 * i;
            const int ar = id >> 3, akc = id & 7;
            CP_ASYNC16(ab + (uint32_t)(ar * QASTR + akc * 4) * 4u,
                       A + (size_t)(m0 + ar) * KU + kt * 32 + akc * 4);
            const int br = id >> 5, bnc = id & 31;
            CP_ASYNC16(bb + (uint32_t)(br * QBSTR + bnc * 4) * 4u,
                       W3b + (size_t)(kt * 32 + br) * QKV_N + n0 + bnc * 4);
        }
    };

    load_tile(0, 0);
    CP_COMMIT();
    load_tile(1, 1);
    CP_COMMIT();

    for (int kt = 0; kt < NK; kt++) {
        const int st = kt - (kt / 3) * 3;
        CP_WAIT(1);
        __syncthreads();
        if (kt + 2 < NK) {
            const int s2 = (kt + 2) - ((kt + 2) / 3) * 3;
            load_tile(kt + 2, s2);
        }
        CP_COMMIT();

        const uint32_t aWarp = s0 + (uint32_t)(st * QSTG_U + wm * QASTR) * 4u + aLane;
        const uint32_t* Bb = smq + st * QSTG_U + QA_TILE;
#pragma unroll
        for (int ks = 0; ks < 4; ks++) {
            uint32_t a[4][4], b[4][2];
#pragma unroll
            for (int fm = 0; fm < 4; fm++)
                ldsm_x4(a[fm], aWarp + (uint32_t)((fm * 16 * QASTR + ks * 8) * 4));
#pragma unroll
            for (int fn = 0; fn < 4; fn++) {
                const uint32_t* q = Bb + (ks * 8 + c) * QBSTR + wn + fn * 8 + r;
                b[fn][0] = q[0];
                b[fn][1] = q[4 * QBSTR];
            }
#pragma unroll
            for (int fm = 0; fm < 4; fm++)
#pragma unroll
                for (int fn = 0; fn < 4; fn++)
                    mma_bf16(acc[fm][fn], a[fm], b[fn][0], b[fn][1]);
        }
    }

    const int sel = n0 >> 10;
    const int nl0 = n0 & 1023;
    __nv_bfloat16* Cb = sel == 0 ? Q : (sel == 1 ? Kout : V);
#pragma unroll
    for (int fm = 0; fm < 4; fm++) {
        const int row0 = m0 + wm + fm * 16 + r;
        const int row1 = row0 + 8;
#pragma unroll
        for (int fn = 0; fn < 4; fn++) {
            const int colg = n0 + wn + fn * 8 + 2 * c;
            const int col  = nl0 + wn + fn * 8 + 2 * c;
            float2 bi = *(const float2*)&bias[colg];
            *(uint32_t*)&Cb[(size_t)row0 * 1024 + col] =
                pack_bf16(acc[fm][fn][0] + bi.x, acc[fm][fn][1] + bi.y);
            *(uint32_t*)&Cb[(size_t)row1 * 1024 + col] =
                pack_bf16(acc[fm][fn][2] + bi.x, acc[fm][fn][3] + bi.y);
        }
    }
}

// ---- fp16 generic GEMM ----
template<bool RELU, bool RES, bool OUT16>
__global__ __launch_bounds__(256, 2) void mm_f16k(
    const uint32_t* __restrict__ A, const uint32_t* __restrict__ Wp,
    const float* __restrict__ bias, const float* __restrict__ Rsd,
    float* __restrict__ Cf, uint32_t* __restrict__ Ch,
    int M, int N, int KU)
{
    extern __shared__ uint32_t smq[];

    const int tid  = threadIdx.x;
    const int warp = tid >> 5, lane = tid & 31;
    const int r = lane >> 2, c = lane & 3;
    const int wm = (warp >> 2) * 64, wn = (warp & 3) * 32;
    const int m0 = blockIdx.y * 128, n0 = blockIdx.x * 128;

    const uint32_t s0 = smem_u32(smq);
    const int g2 = lane >> 3, rowin = lane & 7;
    const uint32_t aLane = (uint32_t)(((g2 & 1) * 8 + rowin) * QASTR + (g2 >> 1) * 4) * 4u;

    float acc[4][4][4];
#pragma unroll
    for (int i = 0; i < 4; i++)
#pragma unroll
        for (int j = 0; j < 4; j++)
#pragma unroll
            for (int k = 0; k < 4; k++) acc[i][j][k] = 0.f;

    const int NK = KU >> 5;

    auto load_tile = [&](int kt, int st) {
        const uint32_t ab = s0 + (uint32_t)(st * QSTG_U) * 4u;
        const uint32_t bb = ab + (uint32_t)QA_TILE * 4u;
#pragma unroll
        for (int i = 0; i < 4; i++) {
            const int id = tid + 256 * i;
            const int ar = id >> 3, akc = id & 7;
            CP_ASYNC16(ab + (uint32_t)(ar * QASTR + akc * 4) * 4u,
                       A + (size_t)(m0 + ar) * KU + kt * 32 + akc * 4);
            const int br = id >> 5, bnc = id & 31;
            CP_ASYNC16(bb + (uint32_t)(br * QBSTR + bnc * 4) * 4u,
                       Wp + (size_t)(kt * 32 + br) * N + n0 + bnc * 4);
        }
    };

    load_tile(0, 0);
    CP_COMMIT();
    load_tile(1, 1);
    CP_COMMIT();

    for (int kt = 0; kt < NK; kt++) {
        const int st = kt - (kt / 3) * 3;
        CP_WAIT(1);
        __syncthreads();
        if (kt + 2 < NK) {
            const int s2 = (kt + 2) - ((kt + 2) / 3) * 3;
            load_tile(kt + 2, s2);
        }
        CP_COMMIT();

        const uint32_t aWarp = s0 + (uint32_t)(st * QSTG_U + wm * QASTR) * 4u + aLane;
        const uint32_t* Bb = smq + st * QSTG_U + QA_TILE;
#pragma unroll
        for (int ks = 0; ks < 4; ks++) {
            uint32_t a[4][4], b[4][2];
#pragma unroll
            for (int fm = 0; fm < 4; fm++)
                ldsm_x4(a[fm], aWarp + (uint32_t)((fm * 16 * QASTR + ks * 8) * 4));
#pragma unroll
            for (int fn = 0; fn < 4; fn++) {
                const uint32_t* q = Bb + (ks * 8 + c) * QBSTR + wn + fn * 8 + r;
                b[fn][0] = q[0];
                b[fn][1] = q[4 * QBSTR];
            }
#pragma unroll
            for (int fm = 0; fm < 4; fm++)
#pragma unroll
                for (int fn = 0; fn < 4; fn++)
                    mma_f16(acc[fm][fn], a[fm], b[fn][0], b[fn][1]);
        }
    }

#pragma unroll
    for (int fm = 0; fm < 4; fm++) {
        const int row0 = m0 + wm + fm * 16 + r;
        const int row1 = row0 + 8;
#pragma unroll
        for (int fn = 0; fn < 4; fn++) {
            const int col = n0 + wn + fn * 8 + 2 * c;
            float2 bi = *(const float2*)&bias[col];
            float v0 = acc[fm][fn][0] + bi.x;
            float v1 = acc[fm][fn][1] + bi.y;
            float v2 = acc[fm][fn][2] + bi.x;
            float v3 = acc[fm][fn][3] + bi.y;
            if (RELU) {
                v0 = fmaxf(v0, 0.f); v1 = fmaxf(v1, 0.f);
                v2 = fmaxf(v2, 0.f); v3 = fmaxf(v3, 0.f);
            }
            if (RES) {
                float2 r0 = *(const float2*)&Rsd[(size_t)row0 * N + col];
                float2 r1 = *(const float2*)&Rsd[(size_t)row1 * N + col];
                v0 += r0.x; v1 += r0.y; v2 += r1.x; v3 += r1.y;
            }
            if (OUT16) {
                const int cu = (col >> 1);
                Ch[(size_t)row0 * (N >> 1) + cu] = pack_f16(v0, v1);
                Ch[(size_t)row1 * (N >> 1) + cu] = pack_f16(v2, v3);
            } else {
                *(float2*)&Cf[(size_t)row0 * N + col] = make_float2(v0, v1);
                *(float2*)&Cf[(size_t)row1 * N + col] = make_float2(v2, v3);
            }
        }
    }
}

// ---------------------------------------------------------------------------
// Flash attention, bf16 m16n8k16. grid = (S/128, H), 128 threads, 2 CTAs/SM.
// 128-key double-buffered K tile; V as [2 buf][2 half][64 dims][36 u32].
// Two 64-key compute chunks per barrier (R14-identical math per chunk).
// ---------------------------------------------------------------------------
#define ASTRU 36
#define QTILE_U (128 * ASTRU)
#define KTILE_U (128 * ASTRU)              // K: 128 keys x 36 u32
#define VT_U    (64 * ASTRU)               // V half-tile: 64 dims x 36 u32
#define ATT_SMEM ((QTILE_U + 2 * KTILE_U + 4 * VT_U) * 4)   // 18+36+36 KB = 90KB
#define QK_SCALE 0.1803368801111364f       // 0.125 * log2(e)

__global__ __launch_bounds__(128, 2) void attn_bf16(
    const __nv_bfloat16* __restrict__ Qm, const __nv_bfloat16* __restrict__ Km,
    const __nv_bfloat16* __restrict__ Vt, uint32_t* __restrict__ CtxH)
{
    extern __shared__ uint32_t su[];
    uint32_t* Qs = su;
    uint32_t* Ks = Qs + QTILE_U;           // [2][128 keys][36]
    uint32_t* Vs = Ks + 2 * KTILE_U;       // [2][2 half][64 dims][36]

    const int tid  = threadIdx.x;
    const int warp = tid >> 5, lane = tid & 31;
    const int r = lane >> 2, c = lane & 3;
    const int wr = warp * 32;
    const int qb = blockIdx.x, h = blockIdx.y;
    const int cb = h * DK;

    const uint32_t qdst = smem_u32(Qs);
    const uint32_t kdst = smem_u32(Ks);
    const uint32_t vdst = smem_u32(Vs);

    const int g2 = lane >> 3, rowin = lane & 7;
    const uint32_t qLane = (uint32_t)(((g2 & 1) * 8 + rowin) * ASTRU + (g2 >> 1) * 4) * 4u;
    const uint32_t kLane = (uint32_t)(rowin * ASTRU + (g2 & 1) * 4) * 4u;

    // load 128-key K/V tile `bt` into buffer `nb`
    auto load_kv = [&](int bt, int nb) {
        // K: 128 key-rows x 8 chunks (1024 chunks)
#pragma unroll
        for (int i = 0; i < 8; i++) {
            int id = tid + 128 * i;
            int row = id >> 3, ch = id & 7;             // key row 0..127
            CP_ASYNC16(kdst + (uint32_t)(nb * KTILE_U + row * ASTRU + ch * 4) * 4u,
                       Km + (size_t)(bt * 128 + row) * D_MODEL + cb + ch * 8);
        }
        // V: 2 halves x 64 dim-rows x 8 chunks (1024 chunks)
#pragma unroll
        for (int i = 0; i < 8; i++) {
            int id = tid + 128 * i;
            int half = id >> 9;                          // 0..1
            int rem  = id & 511;
            int dim  = rem >> 3, ch = rem & 7;           // dim 0..63
            CP_ASYNC16(vdst + (uint32_t)((nb * 2 + half) * VT_U + dim * ASTRU + ch * 4) * 4u,
                       Vt + (size_t)(cb + dim) * S_LEN + bt * 128 + half * 64 + ch * 8);
        }
    };

    // stage Q + K/V tile 0
#pragma unroll
    for (int i = 0; i < 8; i++) {
        int id = tid + 128 * i;
        int row = id >> 3, ch = id & 7;
        CP_ASYNC16(qdst + (uint32_t)(row * ASTRU + ch * 4) * 4u,
                   Qm + (size_t)(qb * 128 + row) * D_MODEL + cb + ch * 8);
    }
    load_kv(0, 0);
    CP_COMMIT();
    CP_WAIT(0);
    __syncthreads();

    const uint32_t qWarp = qdst + (uint32_t)(wr * ASTRU) * 4u + qLane;

    float mrow[2][2] = {{-1e30f, -1e30f}, {-1e30f, -1e30f}};
    float lrow[2][2] = {{0.f, 0.f}, {0.f, 0.f}};
    float acc[2][8][4];
#pragma unroll
    for (int i = 0; i < 2; i++)
#pragma unroll
        for (int j = 0; j < 8; j++)
#pragma unroll
            for (int k = 0; k < 4; k++) acc[i][j][k] = 0.f;

    for (int bt = 0; bt < S_LEN / 128; bt++) {
        const int buf = bt & 1;

        if (bt > 0) {
            CP_WAIT(0);
            __syncthreads();
        }
        if (bt + 1 < S_LEN / 128) {
            load_kv(bt + 1, buf ^ 1);
            CP_COMMIT();
        }

#pragma unroll
        for (int half = 0; half < 2; half++) {
            const uint32_t kTile = kdst +
                (uint32_t)(buf * KTILE_U + half * 64 * ASTRU) * 4u + kLane;
            const uint32_t vTile = vdst +
                (uint32_t)((buf * 2 + half) * VT_U) * 4u + kLane;

            float s[2][8][4];
#pragma unroll
            for (int i = 0; i < 2; i++)
#pragma unroll
                for (int j = 0; j < 8; j++)
#pragma unroll
                    for (int k = 0; k < 4; k++) s[i][j][k] = 0.f;

#pragma unroll
            for (int ks = 0; ks < 4; ks++) {
                uint32_t qf0[4], qf1[4];
                ldsm_x4(qf0, qWarp + (uint32_t)((ks * 8) * 4));
                ldsm_x4(qf1, qWarp + (uint32_t)((16 * ASTRU + ks * 8) * 4));
#pragma unroll
                for (int fn = 0; fn < 8; fn++) {
                    uint32_t b0, b1;
                    ldsm_x2(b0, b1, kTile + (uint32_t)((8 * fn * ASTRU + ks * 8) * 4));
                    mma_bf16(s[0][fn], qf0, b0, b1);
                    mma_bf16(s[1][fn], qf1, b0, b1);
                }
            }

            uint32_t pa[2][4][4];
#pragma unroll
            for (int fm = 0; fm < 2; fm++) {
                float mx0 = -1e30f, mx1 = -1e30f;
#pragma unroll
                for (int fn = 0; fn < 8; fn++) {
                    mx0 = fmaxf(mx0, fmaxf(s[fm][fn][0], s[fm][fn][1]));
                    mx1 = fmaxf(mx1, fmaxf(s[fm][fn][2], s[fm][fn][3]));
                }
                mx0 = fmaxf(mx0, __shfl_xor_sync(0xffffffffu, mx0, 1));
                mx0 = fmaxf(mx0, __shfl_xor_sync(0xffffffffu, mx0, 2));
                mx1 = fmaxf(mx1, __shfl_xor_sync(0xffffffffu, mx1, 1));
                mx1 = fmaxf(mx1, __shfl_xor_sync(0xffffffffu, mx1, 2));

                const float mn0 = fmaxf(mrow[fm][0], mx0);
                const float mn1 = fmaxf(mrow[fm][1], mx1);
                const float emn0 = mn0 * QK_SCALE;
                const float emn1 = mn1 * QK_SCALE;
                const float sc0 = ex2(fmaf(mrow[fm][0], QK_SCALE, -emn0));
                const float sc1 = ex2(fmaf(mrow[fm][1], QK_SCALE, -emn1));
                float ls0 = 0.f, ls1 = 0.f;
#pragma unroll
                for (int fn = 0; fn < 8; fn++) {
                    float e0 = ex2(fmaf(s[fm][fn][0], QK_SCALE, -emn0));
                    float e1 = ex2(fmaf(s[fm][fn][1], QK_SCALE, -emn0));
                    float e2 = ex2(fmaf(s[fm][fn][2], QK_SCALE, -emn1));
                    float e3 = ex2(fmaf(s[fm][fn][3], QK_SCALE, -emn1));
                    ls0 += e0 + e1;
                    ls1 += e2 + e3;
                    pa[fm][fn >> 1][(fn & 1) * 2 + 0] = pack_bf16(e0, e1);
                    pa[fm][fn >> 1][(fn & 1) * 2 + 1] = pack_bf16(e2, e3);
                }
                ls0 += __shfl_xor_sync(0xffffffffu, ls0, 1);
                ls0 += __shfl_xor_sync(0xffffffffu, ls0, 2);
                ls1 += __shfl_xor_sync(0xffffffffu, ls1, 1);
                ls1 += __shfl_xor_sync(0xffffffffu, ls1, 2);

                lrow[fm][0] = lrow[fm][0] * sc0 + ls0;
                lrow[fm][1] = lrow[fm][1] * sc1 + ls1;
                mrow[fm][0] = mn0; mrow[fm][1] = mn1;

#pragma unroll
                for (int fn = 0; fn < 8; fn++) {
                    acc[fm][fn][0] *= sc0; acc[fm][fn][1] *= sc0;
                    acc[fm][fn][2] *= sc1; acc[fm][fn][3] *= sc1;
                }
            }

#pragma unroll
            for (int ks = 0; ks < 4; ks++) {
#pragma unroll
                for (int fn = 0; fn < 8; fn++) {
                    uint32_t b0, b1;
                    ldsm_x2(b0, b1, vTile + (uint32_t)((8 * fn * ASTRU + ks * 8) * 4));
                    mma_bf16(acc[0][fn], pa[0][ks], b0, b1);
                    mma_bf16(acc[1][fn], pa[1][ks], b0, b1);
                }
            }
        }
    }

#pragma unroll
    for (int fm = 0; fm < 2; fm++) {
        const float inv0 = 1.f / lrow[fm][0];
        const float inv1 = 1.f / lrow[fm][1];
        const int row0 = qb * 128 + wr + fm * 16 + r;
        const int row1 = row0 + 8;
#pragma unroll
        for (int fn = 0; fn < 8; fn++) {
            const int cu = ((cb + fn * 8) >> 1) + c;
            CtxH[(size_t)row0 * (D_MODEL / 2) + cu] =
                pack_f16(acc[fm][fn][0] * inv0, acc[fm][fn][1] * inv0);
            CtxH[(size_t)row1 * (D_MODEL / 2) + cu] =
                pack_f16(acc[fm][fn][2] * inv1, acc[fm][fn][3] * inv1);
        }
    }
}

// ---------------------------------------------------------------------------
extern "C" void kernel_launch(void* const* d_in, const int* in_sizes, int n_in,
                              void* d_out, int out_size)
{
    const float* x    = (const float*)d_in[0];
    const float* Wq   = (const float*)d_in[1];
    const float* bq   = (const float*)d_in[2];
    const float* Wk   = (const float*)d_in[3];
    const float* bk   = (const float*)d_in[4];
    const float* Wv   = (const float*)d_in[5];
    const float* bv   = (const float*)d_in[6];
    const float* Wo   = (const float*)d_in[7];
    const float* bo   = (const float*)d_in[8];
    const float* ln1a = (const float*)d_in[9];
    const float* ln1b = (const float*)d_in[10];
    const float* W1   = (const float*)d_in[11];
    const float* b1   = (const float*)d_in[12];
    const float* W2   = (const float*)d_in[13];
    const float* b2   = (const float*)d_in[14];
    const float* ln2a = (const float*)d_in[15];
    const float* ln2b = (const float*)d_in[16];
    float* out = (float*)d_out;

    float *x1, *b3;
    __nv_bfloat16 *h1b, *Qb, *Kb, *Vb, *Vt;
    uint32_t *W3b, *ctxh, *h2h, *f1h, *WoP, *W1P, *W2P;
    cudaGetSymbolAddress((void**)&h1b,  g_h1b);
    cudaGetSymbolAddress((void**)&Qb,   g_Qb);
    cudaGetSymbolAddress((void**)&Kb,   g_Kb);
    cudaGetSymbolAddress((void**)&Vb,   g_Vb);
    cudaGetSymbolAddress((void**)&Vt,   g_Vt);
    cudaGetSymbolAddress((void**)&ctxh, g_ctxh);
    cudaGetSymbolAddress((void**)&x1,   g_x1);
    cudaGetSymbolAddress((void**)&h2h,  g_h2h);
    cudaGetSymbolAddress((void**)&f1h,  g_f1h);
    cudaGetSymbolAddress((void**)&W3b,  g_W3b);
    cudaGetSymbolAddress((void**)&b3,   g_b3);
    cudaGetSymbolAddress((void**)&WoP,  g_WoP);
    cudaGetSymbolAddress((void**)&W1P,  g_W1P);
    cudaGetSymbolAddress((void**)&W2P,  g_W2P);

    cudaFuncSetAttribute(mm_qkv_bf16,
                         cudaFuncAttributeMaxDynamicSharedMemorySize, G16_SMEM);
    cudaFuncSetAttribute(mm_f16k<false, true, false>,
                         cudaFuncAttributeMaxDynamicSharedMemorySize, G16_SMEM);
    cudaFuncSetAttribute(mm_f16k<true, false, true>,
                         cudaFuncAttributeMaxDynamicSharedMemorySize, G16_SMEM);
    cudaFuncSetAttribute(attn_bf16,
                         cudaFuncAttributeMaxDynamicSharedMemorySize, ATT_SMEM);

    // one-time packs
    concat3b<<<(D_MODEL / 2) * QKV_N / 1024, 256>>>(Wq, Wk, Wv, bq, bk, bv, W3b, b3);
    pack_all<<<(PACK_Q0 + PACK_Q1 + PACK_Q2) / 256, 256>>>(Wo, W1, W2, WoP, W1P, W2P);

    const dim3 gQKV (QKV_N  / 128, S_LEN / 128);     // (24, 32)
    const dim3 gSmall(D_MODEL / 128, S_LEN / 128);   // (8, 32)
    const dim3 gFF1 (D_FF   / 128, S_LEN / 128);     // (32, 32)

    // residual 1
    ln_kernel<1><<<S_LEN, 256>>>(x, ln1a, ln1b, h1b);
    mm_qkv_bf16<<<gQKV, 256, G16_SMEM>>>((const uint32_t*)h1b, W3b, b3, Qb, Kb, Vb);
    vtrans_b<<<dim3(S_LEN / 64, D_MODEL / 32), 256>>>(Vb, Vt);
    attn_bf16<<<dim3(S_LEN / 128, NUM_HEADS), 128, ATT_SMEM>>>(Qb, Kb, Vt, ctxh);
    mm_f16k<false, true, false><<<gSmall, 256, G16_SMEM>>>(
        ctxh, WoP, bo, x, x1, nullptr, S_LEN, D_MODEL, D_MODEL / 2);

    // residual 2
    ln_kernel<2><<<S_LEN, 256>>>(x1, ln2a, ln2b, h2h);
    mm_f16k<true, false, true><<<gFF1, 256, G16_SMEM>>>(
        h2h, W1P, b1, nullptr, nullptr, f1h, S_LEN, D_FF, D_MODEL / 2);
    mm_f16k<false, true, false><<<gSmall, 256, G16_SMEM>>>(
        f1h, W2P, b2, x1, out, nullptr, S_LEN, D_MODEL, D_FF / 2);
}